// round 11
// baseline (speedup 1.0000x reference)
#include <cuda_runtime.h>
#include <cstdint>
#include <cstddef>

// Problem constants
#define B_WIN  200
#define S_DIM  14
#define HW     196           // 14*14
#define C_DIM  768
#define NH     12
#define HD     64
#define M_TOK  (B_WIN * HW)  // 39200
#define QKV_N  (3 * C_DIM)   // 2304
#define NHEADS_TOT (B_WIN * NH)   // 2400

// Scratch (device globals: allocation-free per harness rules)
__device__ float g_qkv[(size_t)M_TOK * QKV_N];          // (B*HW, 2304)
__device__ float g_ctx[(size_t)M_TOK * C_DIM];          // (B*HW, 768) tf32-rounded
__device__ float g_at[(size_t)NHEADS_TOT * HW * 200];   // probs (tf32), row stride 200
__device__ float g_xc[(size_t)M_TOK * C_DIM];           // x, tf32-rounded
__device__ float g_wqkvT[(size_t)QKV_N * C_DIM];        // w_qkv^T [N][K], tf32-rounded
__device__ float g_wprojT[(size_t)C_DIM * C_DIM];       // w_proj^T [N][K], tf32-rounded

// ---------------------------------------------------------------------------
// tf32 helpers
// ---------------------------------------------------------------------------
__device__ __forceinline__ float f2tf32(float x) {
    uint32_t r;
    asm("cvt.rna.tf32.f32 %0, %1;" : "=r"(r) : "f"(x));
    return __uint_as_float(r);
}

__device__ __forceinline__ void mma_tf32(float* c, const uint32_t* a, const uint32_t* b) {
    asm volatile(
        "mma.sync.aligned.m16n8k8.row.col.f32.tf32.tf32.f32 "
        "{%0,%1,%2,%3}, {%4,%5,%6,%7}, {%8,%9}, {%0,%1,%2,%3};"
        : "+f"(c[0]), "+f"(c[1]), "+f"(c[2]), "+f"(c[3])
        : "r"(a[0]), "r"(a[1]), "r"(a[2]), "r"(a[3]),
          "r"(b[0]), "r"(b[1]));
}

__device__ __forceinline__ void ldsm_x4(uint32_t& r0, uint32_t& r1,
                                        uint32_t& r2, uint32_t& r3, uint32_t addr) {
    asm volatile("ldmatrix.sync.aligned.m8n8.x4.shared.b16 {%0,%1,%2,%3}, [%4];"
                 : "=r"(r0), "=r"(r1), "=r"(r2), "=r"(r3) : "r"(addr));
}

// ---------------------------------------------------------------------------
// Pre-pass 1: tf32-round a buffer (float4 grid-stride).
// ---------------------------------------------------------------------------
__global__ void cvt_tf32_kernel(const float* __restrict__ src,
                                float* __restrict__ dst, int n4) {
    int i = blockIdx.x * blockDim.x + threadIdx.x;
    int stride = gridDim.x * blockDim.x;
    for (; i < n4; i += stride) {
        float4 v = *(const float4*)(src + (size_t)i * 4);
        v.x = f2tf32(v.x); v.y = f2tf32(v.y); v.z = f2tf32(v.z); v.w = f2tf32(v.w);
        *(float4*)(dst + (size_t)i * 4) = v;
    }
}

// ---------------------------------------------------------------------------
// Pre-pass 2: transpose + tf32-round. src [K][N] -> dst [N][K].
// ---------------------------------------------------------------------------
__global__ void transpose_tf32_kernel(const float* __restrict__ src,
                                      float* __restrict__ dst, int K, int N) {
    __shared__ float t[32][33];
    const int nb = blockIdx.x * 32;
    const int kb = blockIdx.y * 32;
    const int tx = threadIdx.x, ty = threadIdx.y;
#pragma unroll
    for (int i = 0; i < 32; i += 8)
        t[ty + i][tx] = f2tf32(src[(size_t)(kb + ty + i) * N + nb + tx]);
    __syncthreads();
#pragma unroll
    for (int i = 0; i < 32; i += 8)
        dst[(size_t)(nb + ty + i) * K + kb + tx] = t[tx][ty + i];
}

// ---------------------------------------------------------------------------
// Tensor-core tf32 GEMM (transposed-operand form), 3-stage cp.async pipeline,
// ONE __syncthreads per k-tile, ldmatrix fragment loads with REGISTER
// DOUBLE-BUFFERING across ks steps (prefetch ks+1 frags before mma of ks).
// C[M][N] = X[M][K] @ W[K][N] + bias; WT = W^T [N][K] pre-transposed.
// ---------------------------------------------------------------------------
#define BMT 128
#define BNT 128
#define BKT 32
#define XW_STR 36
#define TILE_SZ (128 * XW_STR)              // floats per (X or W) stage
#define G_STAGES 3
#define G_SMEM_FLOATS (2 * G_STAGES * TILE_SZ)
#define G_SMEM_BYTES  (G_SMEM_FLOATS * 4)   // 110592

__global__ __launch_bounds__(256, 2)
void gemm_tf32_bias_t(const float* __restrict__ X,   // [M][K] tf32-rounded
                      const float* __restrict__ WT,  // [N][K] tf32-rounded
                      const float* __restrict__ bias,
                      float* __restrict__ C,
                      int M, int N, int K) {
    extern __shared__ float sg[];
    float* XsBase = sg;                         // [3][128][36]
    float* WsBase = sg + G_STAGES * TILE_SZ;    // [3][128][36]

    const int tid  = threadIdx.x;
    const int warp = tid >> 5;
    const int lane = tid & 31;
    const int g    = lane >> 2;
    const int tig  = lane & 3;
    const int wtn  = warp >> 1;      // 0..3 : n-offset 32
    const int wtm  = warp & 1;       // 0..1 : m-offset 64
    const int m0   = blockIdx.y * BMT;
    const int n0   = blockIdx.x * BNT;

    const uint32_t smemX = (uint32_t)__cvta_generic_to_shared(XsBase);
    const uint32_t smemW = (uint32_t)__cvta_generic_to_shared(WsBase);

    const int lrA = (lane & 7) + ((lane >> 3) & 1) * 8;
    const int lcA = (lane >> 4) * 4;
    const int lrB = (lane & 7) + (lane >> 4) * 8;
    const int lcB = ((lane >> 3) & 1) * 4;

    const uint32_t aBase = smemW + (uint32_t)(((wtn * 32 + lrA) * XW_STR + lcA) << 2);
    const uint32_t bBase = smemX + (uint32_t)(((wtm * 64 + lrB) * XW_STR + lcB) << 2);

    float acc[2][8][4];
#pragma unroll
    for (int i = 0; i < 2; i++)
#pragma unroll
        for (int j = 0; j < 8; j++)
#pragma unroll
            for (int q = 0; q < 4; q++) acc[i][j][q] = 0.f;

    const int T = K / BKT;

    auto stage = [&](int kt, int st) {
#pragma unroll
        for (int i = 0; i < 4; i++) {
            int pos = tid + i * 256;
            int r   = pos >> 3;
            int cv  = (pos & 7) * 4;
            uint32_t dst = smemX + (uint32_t)((st * TILE_SZ + r * XW_STR + cv) << 2);
            const float* src = X + (size_t)(m0 + r) * K + kt + cv;
            int sz = (m0 + r < M) ? 16 : 0;
            asm volatile("cp.async.cg.shared.global [%0], [%1], 16, %2;\n"
                         :: "r"(dst), "l"(src), "r"(sz));
        }
#pragma unroll
        for (int i = 0; i < 4; i++) {
            int pos = tid + i * 256;
            int r   = pos >> 3;
            int cv  = (pos & 7) * 4;
            uint32_t dst = smemW + (uint32_t)((st * TILE_SZ + r * XW_STR + cv) << 2);
            const float* src = WT + (size_t)(n0 + r) * K + kt + cv;
            asm volatile("cp.async.cg.shared.global [%0], [%1], 16, 16;\n"
                         :: "r"(dst), "l"(src));
        }
        asm volatile("cp.async.commit_group;\n");
    };

    // fragment loader for one ks step (6 ldmatrix.x4)
    auto load_frags = [&](uint32_t stOff, int ks, uint32_t a[2][4], uint32_t b[8][2]) {
        const uint32_t kOff = (uint32_t)(ks * 8 * 4);
#pragma unroll
        for (int i = 0; i < 2; i++)
            ldsm_x4(a[i][0], a[i][1], a[i][2], a[i][3],
                    aBase + stOff + (uint32_t)(i * 16 * XW_STR * 4) + kOff);
#pragma unroll
        for (int j2 = 0; j2 < 4; j2++)
            ldsm_x4(b[2 * j2][0], b[2 * j2][1], b[2 * j2 + 1][0], b[2 * j2 + 1][1],
                    bBase + stOff + (uint32_t)(j2 * 16 * XW_STR * 4) + kOff);
    };

    stage(0, 0);
    if (T > 1) stage(BKT, 1);

    for (int kt = 0; kt < T; kt++) {
        const int st = kt % 3;
        if (kt + 1 < T) {
            asm volatile("cp.async.wait_group 1;\n");
        } else {
            asm volatile("cp.async.wait_group 0;\n");
        }
        __syncthreads();

        const uint32_t stOff = (uint32_t)(st * TILE_SZ * 4);

        // issue compute-critical fragment loads FIRST, then refill cp.async
        uint32_t afr[2][2][4], bfr[2][8][2];
        load_frags(stOff, 0, afr[0], bfr[0]);

        if (kt + 2 < T) stage((kt + 2) * BKT, (kt + 2) % 3);

#pragma unroll
        for (int ks = 0; ks < 4; ks++) {
            const int cur = ks & 1;
            const int nxt = cur ^ 1;
            if (ks < 3) load_frags(stOff, ks + 1, afr[nxt], bfr[nxt]);
#pragma unroll
            for (int i = 0; i < 2; i++)
#pragma unroll
                for (int j = 0; j < 8; j++)
                    mma_tf32(acc[i][j], afr[cur][i], bfr[cur][j]);
        }
    }

#pragma unroll
    for (int i = 0; i < 2; i++) {
        const int na = n0 + wtn * 32 + i * 16 + g;
        const int nb = na + 8;
        const float bva = bias[na];
        const float bvb = bias[nb];
#pragma unroll
        for (int j = 0; j < 8; j++) {
            const int ma = m0 + wtm * 64 + j * 8 + 2 * tig;
            if (ma < M) {
                C[(size_t)ma * N + na] = acc[i][j][0] + bva;
                C[(size_t)ma * N + nb] = acc[i][j][2] + bvb;
            }
            if (ma + 1 < M) {
                C[(size_t)(ma + 1) * N + na] = acc[i][j][1] + bva;
                C[(size_t)(ma + 1) * N + nb] = acc[i][j][3] + bvb;
            }
        }
    }
}

// ---------------------------------------------------------------------------
// Kernel L: logits + bias + softmax -> probs. grid = 2400 (bh); loops the
// 4 q-blocks so K and rel tables are staged ONCE per (b,h). (unchanged)
// ---------------------------------------------------------------------------
#define KS_STR 68
#define T_STR  36

#define L_KS    0
#define L_QT    (L_KS  + 200 * KS_STR)
#define L_RPHT  (L_QT  + 64 * KS_STR)
#define L_RPWT  (L_RPHT + 64 * T_STR)
#define L_TH    (L_RPWT + 64 * T_STR)
#define L_TW    (L_TH  + 64 * T_STR)
#define L_REDA  (L_TW  + 64 * T_STR)
#define L_REDB  (L_REDA + 128)
#define L_QHW   (L_REDB + 128)
#define L_SMEM_FLOATS (L_QHW + 128)
#define L_SMEM_BYTES  (L_SMEM_FLOATS * 4)

__global__ __launch_bounds__(256, 2)
void attn_logits_kernel(const float* __restrict__ qkv,
                        const float* __restrict__ rph,
                        const float* __restrict__ rpw,
                        float* __restrict__ at_g) {
    extern __shared__ float sm[];
    float* Ks   = sm + L_KS;
    float* Qt   = sm + L_QT;
    float* rphT = sm + L_RPHT;
    float* rpwT = sm + L_RPWT;
    float* Th   = sm + L_TH;
    float* Tw   = sm + L_TW;
    float* redA = sm + L_REDA;
    float* redB = sm + L_REDB;
    int*   qhw  = (int*)(sm + L_QHW);

    const int bh   = blockIdx.x;
    const int b    = bh / NH;
    const int h    = bh % NH;
    const int tid  = threadIdx.x;
    const int warp = tid >> 5;
    const int lane = tid & 31;
    const int g    = lane >> 2;
    const int tig  = lane & 3;
    const int wm   = warp >> 1;
    const int wn   = warp & 1;
    const float scale = 0.125f;

    const float* qkv_b = qkv + (size_t)b * HW * QKV_N;

    for (int idx = tid; idx < 64 * T_STR; idx += 256) {
        int d = idx / T_STR;
        int j = idx % T_STR;
        rphT[d * T_STR + j] = (j < 2 * S_DIM - 1) ? f2tf32(rph[j * HD + d]) : 0.f;
        rpwT[d * T_STR + j] = (j < 2 * S_DIM - 1) ? f2tf32(rpw[j * HD + d]) : 0.f;
    }
    for (int slot = tid; slot < 200 * 16; slot += 256) {
        int s  = slot >> 4;
        int d4 = (slot & 15) << 2;
        float4 v = make_float4(0.f, 0.f, 0.f, 0.f);
        if (s < HW) {
            v = *(const float4*)(qkv_b + (size_t)s * QKV_N + C_DIM + h * HD + d4);
            v.x = f2tf32(v.x); v.y = f2tf32(v.y); v.z = f2tf32(v.z); v.w = f2tf32(v.w);
        }
        *(float4*)&Ks[s * KS_STR + d4] = v;
    }

    for (int qb = 0; qb < 4; qb++) {
        const int qbase = qb * 64;
        __syncthreads();

        for (int slot = tid; slot < 64 * 16; slot += 256) {
            int ql = slot >> 4;
            int d4 = (slot & 15) << 2;
            int s  = qbase + ql;
            float4 v = make_float4(0.f, 0.f, 0.f, 0.f);
            if (s < HW) {
                v = *(const float4*)(qkv_b + (size_t)s * QKV_N + h * HD + d4);
                v.x = f2tf32(v.x); v.y = f2tf32(v.y); v.z = f2tf32(v.z); v.w = f2tf32(v.w);
            }
            *(float4*)&Qt[ql * KS_STR + d4] = v;
        }
        if (tid < 64) {
            int s = qbase + tid;
            qhw[tid]      = s / S_DIM;
            qhw[64 + tid] = s % S_DIM;
        }
        __syncthreads();

        const int rB = wm * 16;
        uint32_t af[8][4];
#pragma unroll
        for (int kc = 0; kc < 8; kc++) {
            const int kb = kc * 8;
            af[kc][0] = __float_as_uint(Qt[(rB + g    ) * KS_STR + kb + tig    ]);
            af[kc][1] = __float_as_uint(Qt[(rB + g + 8) * KS_STR + kb + tig    ]);
            af[kc][2] = __float_as_uint(Qt[(rB + g    ) * KS_STR + kb + tig + 4]);
            af[kc][3] = __float_as_uint(Qt[(rB + g + 8) * KS_STR + kb + tig + 4]);
        }

        {
            const float* Bt = wn ? rpwT : rphT;
            float*       Dt = wn ? Tw   : Th;
#pragma unroll
            for (int nt = 0; nt < 4; nt++) {
                float acc[4] = {0.f, 0.f, 0.f, 0.f};
                const int col = nt * 8 + g;
#pragma unroll
                for (int kc = 0; kc < 8; kc++) {
                    const int kb = kc * 8;
                    uint32_t bf[2];
                    bf[0] = __float_as_uint(Bt[(kb + tig    ) * T_STR + col]);
                    bf[1] = __float_as_uint(Bt[(kb + tig + 4) * T_STR + col]);
                    mma_tf32(acc, af[kc], bf);
                }
                const int c0 = nt * 8 + 2 * tig;
                Dt[(rB + g    ) * T_STR + c0    ] = acc[0];
                Dt[(rB + g    ) * T_STR + c0 + 1] = acc[1];
                Dt[(rB + g + 8) * T_STR + c0    ] = acc[2];
                Dt[(rB + g + 8) * T_STR + c0 + 1] = acc[3];
            }
        }
        __syncthreads();

        const int r0 = rB + g;
        const int r1 = r0 + 8;
        const int qh0 = qhw[r0],      qw0 = qhw[64 + r0];
        const int qh1 = qhw[r1],      qw1 = qhw[64 + r1];
        float lg[13][4];
#pragma unroll
        for (int it = 0; it < 13; it++) {
            const int nt  = wn * 13 + it;
            float acc[4] = {0.f, 0.f, 0.f, 0.f};
            const int col = nt * 8 + g;
#pragma unroll
            for (int kc = 0; kc < 8; kc++) {
                const int kb = kc * 8;
                uint32_t bf[2];
                bf[0] = __float_as_uint(Ks[col * KS_STR + kb + tig    ]);
                bf[1] = __float_as_uint(Ks[col * KS_STR + kb + tig + 4]);
                mma_tf32(acc, af[kc], bf);
            }
            const int c0 = nt * 8 + 2 * tig;
            const int c1 = c0 + 1;
            if (c0 < HW) {
                int kh = c0 / S_DIM, kw = c0 % S_DIM;
                lg[it][0] = acc[0] * scale + Th[r0 * T_STR + qh0 - kh + 13] + Tw[r0 * T_STR + qw0 - kw + 13];
                lg[it][2] = acc[2] * scale + Th[r1 * T_STR + qh1 - kh + 13] + Tw[r1 * T_STR + qw1 - kw + 13];
            } else { lg[it][0] = -1e30f; lg[it][2] = -1e30f; }
            if (c1 < HW) {
                int kh = c1 / S_DIM, kw = c1 % S_DIM;
                lg[it][1] = acc[1] * scale + Th[r0 * T_STR + qh0 - kh + 13] + Tw[r0 * T_STR + qw0 - kw + 13];
                lg[it][3] = acc[3] * scale + Th[r1 * T_STR + qh1 - kh + 13] + Tw[r1 * T_STR + qw1 - kw + 13];
            } else { lg[it][1] = -1e30f; lg[it][3] = -1e30f; }
        }

        float m0 = -1e30f, m1 = -1e30f;
#pragma unroll
        for (int it = 0; it < 13; it++) {
            m0 = fmaxf(m0, fmaxf(lg[it][0], lg[it][1]));
            m1 = fmaxf(m1, fmaxf(lg[it][2], lg[it][3]));
        }
        m0 = fmaxf(m0, __shfl_xor_sync(0xffffffffu, m0, 1));
        m0 = fmaxf(m0, __shfl_xor_sync(0xffffffffu, m0, 2));
        m1 = fmaxf(m1, __shfl_xor_sync(0xffffffffu, m1, 1));
        m1 = fmaxf(m1, __shfl_xor_sync(0xffffffffu, m1, 2));
        if (tig == 0) { redA[wn * 64 + r0] = m0; redA[wn * 64 + r1] = m1; }
        __syncthreads();
        const float M0 = fmaxf(redA[r0], redA[64 + r0]);
        const float M1 = fmaxf(redA[r1], redA[64 + r1]);

        float s0 = 0.f, s1 = 0.f;
#pragma unroll
        for (int it = 0; it < 13; it++) {
            float e0 = __expf(lg[it][0] - M0); lg[it][0] = e0; s0 += e0;
            float e1 = __expf(lg[it][1] - M0); lg[it][1] = e1; s0 += e1;
            float e2 = __expf(lg[it][2] - M1); lg[it][2] = e2; s1 += e2;
            float e3 = __expf(lg[it][3] - M1); lg[it][3] = e3; s1 += e3;
        }
        s0 += __shfl_xor_sync(0xffffffffu, s0, 1);
        s0 += __shfl_xor_sync(0xffffffffu, s0, 2);
        s1 += __shfl_xor_sync(0xffffffffu, s1, 1);
        s1 += __shfl_xor_sync(0xffffffffu, s1, 2);
        if (tig == 0) { redB[wn * 64 + r0] = s0; redB[wn * 64 + r1] = s1; }
        __syncthreads();
        const float inv0 = 1.0f / (redB[r0] + redB[64 + r0]);
        const float inv1 = 1.0f / (redB[r1] + redB[64 + r1]);

        const int row0 = qbase + r0;
        const int row1 = qbase + r1;
        float* atr0 = at_g + ((size_t)bh * HW + row0) * 200;
        float* atr1 = at_g + ((size_t)bh * HW + row1) * 200;
#pragma unroll
        for (int it = 0; it < 13; it++) {
            const int nt = wn * 13 + it;
            const int c0 = nt * 8 + 2 * tig;
            if (c0 < HW) {
                if (row0 < HW) {
                    float2 p = make_float2(f2tf32(lg[it][0] * inv0), f2tf32(lg[it][1] * inv0));
                    *(float2*)(atr0 + c0) = p;
                }
                if (row1 < HW) {
                    float2 p = make_float2(f2tf32(lg[it][2] * inv1), f2tf32(lg[it][3] * inv1));
                    *(float2*)(atr1 + c0) = p;
                }
            }
        }
    }
}

// ---------------------------------------------------------------------------
// Kernel V: out = probs @ V. ctx stored tf32-rounded. (unchanged)
// ---------------------------------------------------------------------------
#define V_STR  72
#define AT_STR 204
#define V_SMEM_FLOATS (200 * V_STR + 64 * AT_STR)
#define V_SMEM_BYTES  (V_SMEM_FLOATS * 4)

__global__ __launch_bounds__(256, 2)
void attn_av_kernel(const float* __restrict__ qkv,
                    const float* __restrict__ at_g,
                    float* __restrict__ ctx) {
    extern __shared__ float sm[];
    float* Vs  = sm;
    float* atS = sm + 200 * V_STR;

    const int bh   = blockIdx.x;
    const int b    = bh / NH;
    const int h    = bh % NH;
    const int tid  = threadIdx.x;
    const int warp = tid >> 5;
    const int lane = tid & 31;
    const int g    = lane >> 2;
    const int tig  = lane & 3;
    const int wm   = warp >> 1;
    const int wn   = warp & 1;

    const float* qkv_b = qkv + (size_t)b * HW * QKV_N;
    const float* at_b  = at_g + (size_t)bh * HW * 200;

    for (int slot = tid; slot < 200 * 16; slot += 256) {
        int s  = slot >> 4;
        int d4 = (slot & 15) << 2;
        float4 v = make_float4(0.f, 0.f, 0.f, 0.f);
        if (s < HW) {
            v = *(const float4*)(qkv_b + (size_t)s * QKV_N + 2 * C_DIM + h * HD + d4);
            v.x = f2tf32(v.x); v.y = f2tf32(v.y); v.z = f2tf32(v.z); v.w = f2tf32(v.w);
        }
        *(float4*)&Vs[s * V_STR + d4] = v;
    }

    for (int qb = 0; qb < 4; qb++) {
        const int qbase = qb * 64;
        __syncthreads();

        for (int slot = tid; slot < 64 * 50; slot += 256) {
            int rr = slot / 50;
            int c4 = slot % 50;
            int s  = qbase + rr;
            float4 v = make_float4(0.f, 0.f, 0.f, 0.f);
            if (s < HW && c4 < 49)
                v = *(const float4*)(at_b + (size_t)s * 200 + c4 * 4);
            *(float4*)&atS[rr * AT_STR + c4 * 4] = v;
        }
        __syncthreads();

        const int rB = wm * 16;
        float acc[4][4];
#pragma unroll
        for (int nt = 0; nt < 4; nt++)
#pragma unroll
            for (int i = 0; i < 4; i++) acc[nt][i] = 0.f;

        for (int kc = 0; kc < 25; kc++) {
            const int kb = kc * 8;
            uint32_t a[4];
            a[0] = __float_as_uint(atS[(rB + g    ) * AT_STR + kb + tig    ]);
            a[1] = __float_as_uint(atS[(rB + g + 8) * AT_STR + kb + tig    ]);
            a[2] = __float_as_uint(atS[(rB + g    ) * AT_STR + kb + tig + 4]);
            a[3] = __float_as_uint(atS[(rB + g + 8) * AT_STR + kb + tig + 4]);
#pragma unroll
            for (int nt = 0; nt < 4; nt++) {
                const int col = wn * 32 + nt * 8 + g;
                uint32_t bf[2];
                bf[0] = __float_as_uint(Vs[(kb + tig    ) * V_STR + col]);
                bf[1] = __float_as_uint(Vs[(kb + tig + 4) * V_STR + col]);
                mma_tf32(acc[nt], a, bf);
            }
        }

        const int s0 = qbase + rB + g;
        const int s1 = s0 + 8;
#pragma unroll
        for (int nt = 0; nt < 4; nt++) {
            const int d = wn * 32 + nt * 8 + 2 * tig;
            if (s0 < HW) {
                float2 r0 = make_float2(f2tf32(acc[nt][0]), f2tf32(acc[nt][1]));
                *(float2*)(ctx + (size_t)(b * HW + s0) * C_DIM + h * HD + d) = r0;
            }
            if (s1 < HW) {
                float2 r1 = make_float2(f2tf32(acc[nt][2]), f2tf32(acc[nt][3]));
                *(float2*)(ctx + (size_t)(b * HW + s1) * C_DIM + h * HD + d) = r1;
            }
        }
    }
}

// ---------------------------------------------------------------------------
extern "C" void kernel_launch(void* const* d_in, const int* in_sizes, int n_in,
                              void* d_out, int out_size) {
    const float* x      = (const float*)d_in[0];
    const float* w_qkv  = (const float*)d_in[1];
    const float* b_qkv  = (const float*)d_in[2];
    const float* w_proj = (const float*)d_in[3];
    const float* b_proj = (const float*)d_in[4];
    const float* rph    = (const float*)d_in[5];
    const float* rpw    = (const float*)d_in[6];
    float* out = (float*)d_out;

    float *qkv_ptr, *ctx_ptr, *at_ptr, *xc_ptr, *wqT_ptr, *wpT_ptr;
    cudaGetSymbolAddress((void**)&qkv_ptr, g_qkv);
    cudaGetSymbolAddress((void**)&ctx_ptr, g_ctx);
    cudaGetSymbolAddress((void**)&at_ptr, g_at);
    cudaGetSymbolAddress((void**)&xc_ptr, g_xc);
    cudaGetSymbolAddress((void**)&wqT_ptr, g_wqkvT);
    cudaGetSymbolAddress((void**)&wpT_ptr, g_wprojT);

    static bool attr_set = false;
    if (!attr_set) {
        cudaFuncSetAttribute(gemm_tf32_bias_t,
                             cudaFuncAttributeMaxDynamicSharedMemorySize,
                             G_SMEM_BYTES);
        cudaFuncSetAttribute(attn_logits_kernel,
                             cudaFuncAttributeMaxDynamicSharedMemorySize,
                             L_SMEM_BYTES);
        cudaFuncSetAttribute(attn_av_kernel,
                             cudaFuncAttributeMaxDynamicSharedMemorySize,
                             V_SMEM_BYTES);
        attr_set = true;
    }

    // 0) Pre-pass: tf32-round x; transpose + tf32-round weights
    cvt_tf32_kernel<<<592, 256>>>(x, xc_ptr, M_TOK * C_DIM / 4);
    {
        dim3 blk(32, 8);
        dim3 gq(QKV_N / 32, C_DIM / 32);
        transpose_tf32_kernel<<<gq, blk>>>(w_qkv, wqT_ptr, C_DIM, QKV_N);
        dim3 gp(C_DIM / 32, C_DIM / 32);
        transpose_tf32_kernel<<<gp, blk>>>(w_proj, wpT_ptr, C_DIM, C_DIM);
    }

    // 1) QKV projection (3-stage pipeline, fragment double-buffering)
    {
        dim3 grid(QKV_N / BNT, (M_TOK + BMT - 1) / BMT);   // 18 x 307
        gemm_tf32_bias_t<<<grid, 256, G_SMEM_BYTES>>>(xc_ptr, wqT_ptr, b_qkv, qkv_ptr,
                                                      M_TOK, QKV_N, C_DIM);
    }

    // 2a) Logits + bias + softmax -> probs (K staged once per head)
    attn_logits_kernel<<<NHEADS_TOT, 256, L_SMEM_BYTES>>>(qkv_ptr, rph, rpw, at_ptr);

    // 2b) AV (ctx written tf32-rounded)
    attn_av_kernel<<<NHEADS_TOT, 256, V_SMEM_BYTES>>>(qkv_ptr, at_ptr, ctx_ptr);

    // 3) Output projection
    {
        dim3 grid(C_DIM / BNT, (M_TOK + BMT - 1) / BMT);   // 6 x 307
        gemm_tf32_bias_t<<<grid, 256, G_SMEM_BYTES>>>(ctx_ptr, wpT_ptr, b_proj, out,
                                                      M_TOK, C_DIM, C_DIM);
    }
}

// round 13
// speedup vs baseline: 1.4174x; 1.4174x over previous
#include <cuda_runtime.h>
#include <cuda_fp16.h>
#include <cstdint>
#include <cstddef>

// Problem constants
#define B_WIN  200
#define S_DIM  14
#define HW     196           // 14*14
#define C_DIM  768
#define NH     12
#define HD     64
#define M_TOK  (B_WIN * HW)  // 39200
#define QKV_N  (3 * C_DIM)   // 2304
#define NHEADS_TOT (B_WIN * NH)   // 2400

// Scratch (device globals: allocation-free per harness rules)
__device__ float  g_qkv[(size_t)M_TOK * QKV_N];          // (B*HW, 2304) fp32
__device__ float  g_at[(size_t)NHEADS_TOT * HW * 200];   // probs (tf32)
__device__ __half g_xc[(size_t)M_TOK * C_DIM];           // x fp16
__device__ __half g_ctx[(size_t)M_TOK * C_DIM];          // ctx fp16
__device__ __half g_wqT[(size_t)QKV_N * C_DIM];          // w_qkv^T [N][K] fp16
__device__ __half g_wpT[(size_t)C_DIM * C_DIM];          // w_proj^T [N][K] fp16

// ---------------------------------------------------------------------------
// helpers
// ---------------------------------------------------------------------------
__device__ __forceinline__ float f2tf32(float x) {
    uint32_t r;
    asm("cvt.rna.tf32.f32 %0, %1;" : "=r"(r) : "f"(x));
    return __uint_as_float(r);
}

__device__ __forceinline__ void mma_tf32(float* c, const uint32_t* a, const uint32_t* b) {
    asm volatile(
        "mma.sync.aligned.m16n8k8.row.col.f32.tf32.tf32.f32 "
        "{%0,%1,%2,%3}, {%4,%5,%6,%7}, {%8,%9}, {%0,%1,%2,%3};"
        : "+f"(c[0]), "+f"(c[1]), "+f"(c[2]), "+f"(c[3])
        : "r"(a[0]), "r"(a[1]), "r"(a[2]), "r"(a[3]),
          "r"(b[0]), "r"(b[1]));
}

__device__ __forceinline__ void mma_f16(float* c, const uint32_t* a, const uint32_t* b) {
    asm volatile(
        "mma.sync.aligned.m16n8k16.row.col.f32.f16.f16.f32 "
        "{%0,%1,%2,%3}, {%4,%5,%6,%7}, {%8,%9}, {%0,%1,%2,%3};"
        : "+f"(c[0]), "+f"(c[1]), "+f"(c[2]), "+f"(c[3])
        : "r"(a[0]), "r"(a[1]), "r"(a[2]), "r"(a[3]),
          "r"(b[0]), "r"(b[1]));
}

__device__ __forceinline__ void ldsm_x4(uint32_t& r0, uint32_t& r1,
                                        uint32_t& r2, uint32_t& r3, uint32_t addr) {
    asm volatile("ldmatrix.sync.aligned.m8n8.x4.shared.b16 {%0,%1,%2,%3}, [%4];"
                 : "=r"(r0), "=r"(r1), "=r"(r2), "=r"(r3) : "r"(addr));
}

// ---------------------------------------------------------------------------
// Pre-pass 1: fp32 -> fp16.
// ---------------------------------------------------------------------------
__global__ void cvt_half_kernel(const float* __restrict__ src,
                                __half* __restrict__ dst, int n4) {
    int i = blockIdx.x * blockDim.x + threadIdx.x;
    int stride = gridDim.x * blockDim.x;
    for (; i < n4; i += stride) {
        float4 v = *(const float4*)(src + (size_t)i * 4);
        __half2 a = __floats2half2_rn(v.x, v.y);
        __half2 b = __floats2half2_rn(v.z, v.w);
        *(__half2*)(dst + (size_t)i * 4)     = a;
        *(__half2*)(dst + (size_t)i * 4 + 2) = b;
    }
}

// ---------------------------------------------------------------------------
// Pre-pass 2: transpose + fp16. src [K][N] fp32 -> dst [N][K] fp16.
// ---------------------------------------------------------------------------
__global__ void transpose_half_kernel(const float* __restrict__ src,
                                      __half* __restrict__ dst, int K, int N) {
    __shared__ float t[32][33];
    const int nb = blockIdx.x * 32;
    const int kb = blockIdx.y * 32;
    const int tx = threadIdx.x, ty = threadIdx.y;
#pragma unroll
    for (int i = 0; i < 32; i += 8)
        t[ty + i][tx] = src[(size_t)(kb + ty + i) * N + nb + tx];
    __syncthreads();
#pragma unroll
    for (int i = 0; i < 32; i += 8)
        dst[(size_t)(nb + ty + i) * K + kb + tx] = __float2half(t[tx][ty + i]);
}

// ---------------------------------------------------------------------------
// fp16 tensor-core GEMM (transposed-operand form), 3-stage cp.async pipeline,
// one __syncthreads per k-tile, ldmatrix fragments, mma m16n8k16.
// C[M][N] = X[M][K] @ W[K][N] + bias; WT = W^T [N][K] fp16.
// mma A-operand = WT tile (16n x 16k), B-operand = X tile (16k x 8m),
// D = (n x m). BM=128, BN=128, BK=64 (halves). 8 warps: 4 on n x 2 on m.
// SMEM rows: 64 halves data + 8 pad = 144B stride (ldmatrix conflict-free:
// bank step 4/row, 8 rows cover all 32 banks).
// ---------------------------------------------------------------------------
#define BMH 128
#define BNH 128
#define BKH 64
#define H_ROWB 144                 // bytes per smem row
#define OP_B  (128 * H_ROWB)       // 18432 B per operand per stage
#define STAGE_B (2 * OP_B)         // X + W
#define GH_STAGES 3
#define GH_SMEM_BYTES (GH_STAGES * STAGE_B)   // 110592

__global__ __launch_bounds__(256, 2)
void gemm_f16_bias_t(const __half* __restrict__ X,   // [M][K]
                     const __half* __restrict__ WT,  // [N][K]
                     const float* __restrict__ bias,
                     float* __restrict__ C,
                     int M, int N, int K) {
    extern __shared__ __align__(128) char smg[];
    const uint32_t sbase = (uint32_t)__cvta_generic_to_shared(smg);

    const int tid  = threadIdx.x;
    const int warp = tid >> 5;
    const int lane = tid & 31;
    const int g    = lane >> 2;
    const int tig  = lane & 3;
    const int wtn  = warp >> 1;      // 0..3 : n-offset 32
    const int wtm  = warp & 1;       // 0..1 : m-offset 64
    const int m0   = blockIdx.y * BMH;
    const int n0   = blockIdx.x * BNH;

    // ldmatrix lane coords
    // A (WT): m0..m3 = {rows0-7 c0, rows8-15 c0, rows0-7 c16B, rows8-15 c16B}
    const int lrA = (lane & 7) + ((lane >> 3) & 1) * 8;
    const int lcA = ((lane >> 4) & 1) * 16;
    // B (X): m0..m3 = {rows0-7 c0, rows0-7 c16B, rows8-15 c0, rows8-15 c16B}
    const int lrB = (lane & 7) + ((lane >> 4) & 1) * 8;
    const int lcB = ((lane >> 3) & 1) * 16;

    const uint32_t aBase = sbase + OP_B + (uint32_t)((wtn * 32 + lrA) * H_ROWB + lcA);
    const uint32_t bBase = sbase +        (uint32_t)((wtm * 64 + lrB) * H_ROWB + lcB);

    float acc[2][8][4];
#pragma unroll
    for (int i = 0; i < 2; i++)
#pragma unroll
        for (int j = 0; j < 8; j++)
#pragma unroll
            for (int q = 0; q < 4; q++) acc[i][j][q] = 0.f;

    const int T = K / BKH;   // 12

    auto stage = [&](int kb, int st) {
        const uint32_t sOff = sbase + (uint32_t)(st * STAGE_B);
        const int kcol = kb * BKH;
        // X: 128 rows x 8 chunks(16B) = 1024, 4/thread
#pragma unroll
        for (int i = 0; i < 4; i++) {
            int pos = tid + i * 256;
            int r   = pos >> 3;
            int ch  = pos & 7;
            uint32_t dst = sOff + (uint32_t)(r * H_ROWB + ch * 16);
            const void* src = X + (size_t)(m0 + r) * K + kcol + ch * 8;
            int sz = (m0 + r < M) ? 16 : 0;
            asm volatile("cp.async.cg.shared.global [%0], [%1], 16, %2;\n"
                         :: "r"(dst), "l"(src), "r"(sz));
        }
        // WT: always in-bounds
#pragma unroll
        for (int i = 0; i < 4; i++) {
            int pos = tid + i * 256;
            int r   = pos >> 3;
            int ch  = pos & 7;
            uint32_t dst = sOff + (uint32_t)(OP_B + r * H_ROWB + ch * 16);
            const void* src = WT + (size_t)(n0 + r) * K + kcol + ch * 8;
            asm volatile("cp.async.cg.shared.global [%0], [%1], 16, 16;\n"
                         :: "r"(dst), "l"(src));
        }
        asm volatile("cp.async.commit_group;\n");
    };

    stage(0, 0);
    if (T > 1) stage(1, 1);

    for (int kt = 0; kt < T; kt++) {
        const int st = kt % 3;
        if (kt + 1 < T) asm volatile("cp.async.wait_group 1;\n" ::: "memory");
        else            asm volatile("cp.async.wait_group 0;\n" ::: "memory");
        __syncthreads();
        if (kt + 2 < T) stage(kt + 2, (kt + 2) % 3);

        const uint32_t stOff = (uint32_t)(st * STAGE_B);

#pragma unroll
        for (int kc = 0; kc < 4; kc++) {                 // 4 x k16 chunks
            const uint32_t kOff = (uint32_t)(kc * 32);   // 16 halves = 32B
            uint32_t a[2][4];
#pragma unroll
            for (int i = 0; i < 2; i++)
                ldsm_x4(a[i][0], a[i][1], a[i][2], a[i][3],
                        aBase + stOff + (uint32_t)(i * 16 * H_ROWB) + kOff);
            uint32_t b[8][2];
#pragma unroll
            for (int j2 = 0; j2 < 4; j2++)
                ldsm_x4(b[2 * j2][0], b[2 * j2][1], b[2 * j2 + 1][0], b[2 * j2 + 1][1],
                        bBase + stOff + (uint32_t)(j2 * 16 * H_ROWB) + kOff);
#pragma unroll
            for (int i = 0; i < 2; i++)
#pragma unroll
                for (int j = 0; j < 8; j++)
                    mma_f16(acc[i][j], a[i], b[j]);
        }
    }

    // Epilogue: acc[i][j] = D(n x m): c0=(n=g, m=2tig), c1=(g,2tig+1),
    // c2=(g+8,2tig), c3=(g+8,2tig+1). Write C[m][n] + bias[n].
#pragma unroll
    for (int i = 0; i < 2; i++) {
        const int na = n0 + wtn * 32 + i * 16 + g;
        const int nb = na + 8;
        const float bva = bias[na];
        const float bvb = bias[nb];
#pragma unroll
        for (int j = 0; j < 8; j++) {
            const int ma = m0 + wtm * 64 + j * 8 + 2 * tig;
            if (ma < M) {
                C[(size_t)ma * N + na] = acc[i][j][0] + bva;
                C[(size_t)ma * N + nb] = acc[i][j][2] + bvb;
            }
            if (ma + 1 < M) {
                C[(size_t)(ma + 1) * N + na] = acc[i][j][1] + bva;
                C[(size_t)(ma + 1) * N + nb] = acc[i][j][3] + bvb;
            }
        }
    }
}

// ---------------------------------------------------------------------------
// Kernel L: logits + bias + softmax -> probs. grid = 2400 (bh). (unchanged)
// ---------------------------------------------------------------------------
#define KS_STR 68
#define T_STR  36

#define L_KS    0
#define L_QT    (L_KS  + 200 * KS_STR)
#define L_RPHT  (L_QT  + 64 * KS_STR)
#define L_RPWT  (L_RPHT + 64 * T_STR)
#define L_TH    (L_RPWT + 64 * T_STR)
#define L_TW    (L_TH  + 64 * T_STR)
#define L_REDA  (L_TW  + 64 * T_STR)
#define L_REDB  (L_REDA + 128)
#define L_QHW   (L_REDB + 128)
#define L_SMEM_FLOATS (L_QHW + 128)
#define L_SMEM_BYTES  (L_SMEM_FLOATS * 4)

__global__ __launch_bounds__(256, 2)
void attn_logits_kernel(const float* __restrict__ qkv,
                        const float* __restrict__ rph,
                        const float* __restrict__ rpw,
                        float* __restrict__ at_g) {
    extern __shared__ float sm[];
    float* Ks   = sm + L_KS;
    float* Qt   = sm + L_QT;
    float* rphT = sm + L_RPHT;
    float* rpwT = sm + L_RPWT;
    float* Th   = sm + L_TH;
    float* Tw   = sm + L_TW;
    float* redA = sm + L_REDA;
    float* redB = sm + L_REDB;
    int*   qhw  = (int*)(sm + L_QHW);

    const int bh   = blockIdx.x;
    const int b    = bh / NH;
    const int h    = bh % NH;
    const int tid  = threadIdx.x;
    const int warp = tid >> 5;
    const int lane = tid & 31;
    const int g    = lane >> 2;
    const int tig  = lane & 3;
    const int wm   = warp >> 1;
    const int wn   = warp & 1;
    const float scale = 0.125f;

    const float* qkv_b = qkv + (size_t)b * HW * QKV_N;

    for (int idx = tid; idx < 64 * T_STR; idx += 256) {
        int d = idx / T_STR;
        int j = idx % T_STR;
        rphT[d * T_STR + j] = (j < 2 * S_DIM - 1) ? f2tf32(rph[j * HD + d]) : 0.f;
        rpwT[d * T_STR + j] = (j < 2 * S_DIM - 1) ? f2tf32(rpw[j * HD + d]) : 0.f;
    }
    for (int slot = tid; slot < 200 * 16; slot += 256) {
        int s  = slot >> 4;
        int d4 = (slot & 15) << 2;
        float4 v = make_float4(0.f, 0.f, 0.f, 0.f);
        if (s < HW) {
            v = *(const float4*)(qkv_b + (size_t)s * QKV_N + C_DIM + h * HD + d4);
            v.x = f2tf32(v.x); v.y = f2tf32(v.y); v.z = f2tf32(v.z); v.w = f2tf32(v.w);
        }
        *(float4*)&Ks[s * KS_STR + d4] = v;
    }

    for (int qb = 0; qb < 4; qb++) {
        const int qbase = qb * 64;
        __syncthreads();

        for (int slot = tid; slot < 64 * 16; slot += 256) {
            int ql = slot >> 4;
            int d4 = (slot & 15) << 2;
            int s  = qbase + ql;
            float4 v = make_float4(0.f, 0.f, 0.f, 0.f);
            if (s < HW) {
                v = *(const float4*)(qkv_b + (size_t)s * QKV_N + h * HD + d4);
                v.x = f2tf32(v.x); v.y = f2tf32(v.y); v.z = f2tf32(v.z); v.w = f2tf32(v.w);
            }
            *(float4*)&Qt[ql * KS_STR + d4] = v;
        }
        if (tid < 64) {
            int s = qbase + tid;
            qhw[tid]      = s / S_DIM;
            qhw[64 + tid] = s % S_DIM;
        }
        __syncthreads();

        const int rB = wm * 16;
        uint32_t af[8][4];
#pragma unroll
        for (int kc = 0; kc < 8; kc++) {
            const int kb = kc * 8;
            af[kc][0] = __float_as_uint(Qt[(rB + g    ) * KS_STR + kb + tig    ]);
            af[kc][1] = __float_as_uint(Qt[(rB + g + 8) * KS_STR + kb + tig    ]);
            af[kc][2] = __float_as_uint(Qt[(rB + g    ) * KS_STR + kb + tig + 4]);
            af[kc][3] = __float_as_uint(Qt[(rB + g + 8) * KS_STR + kb + tig + 4]);
        }

        {
            const float* Bt = wn ? rpwT : rphT;
            float*       Dt = wn ? Tw   : Th;
#pragma unroll
            for (int nt = 0; nt < 4; nt++) {
                float acc[4] = {0.f, 0.f, 0.f, 0.f};
                const int col = nt * 8 + g;
#pragma unroll
                for (int kc = 0; kc < 8; kc++) {
                    const int kb = kc * 8;
                    uint32_t bf[2];
                    bf[0] = __float_as_uint(Bt[(kb + tig    ) * T_STR + col]);
                    bf[1] = __float_as_uint(Bt[(kb + tig + 4) * T_STR + col]);
                    mma_tf32(acc, af[kc], bf);
                }
                const int c0 = nt * 8 + 2 * tig;
                Dt[(rB + g    ) * T_STR + c0    ] = acc[0];
                Dt[(rB + g    ) * T_STR + c0 + 1] = acc[1];
                Dt[(rB + g + 8) * T_STR + c0    ] = acc[2];
                Dt[(rB + g + 8) * T_STR + c0 + 1] = acc[3];
            }
        }
        __syncthreads();

        const int r0 = rB + g;
        const int r1 = r0 + 8;
        const int qh0 = qhw[r0],      qw0 = qhw[64 + r0];
        const int qh1 = qhw[r1],      qw1 = qhw[64 + r1];
        float lg[13][4];
#pragma unroll
        for (int it = 0; it < 13; it++) {
            const int nt  = wn * 13 + it;
            float acc[4] = {0.f, 0.f, 0.f, 0.f};
            const int col = nt * 8 + g;
#pragma unroll
            for (int kc = 0; kc < 8; kc++) {
                const int kb = kc * 8;
                uint32_t bf[2];
                bf[0] = __float_as_uint(Ks[col * KS_STR + kb + tig    ]);
                bf[1] = __float_as_uint(Ks[col * KS_STR + kb + tig + 4]);
                mma_tf32(acc, af[kc], bf);
            }
            const int c0 = nt * 8 + 2 * tig;
            const int c1 = c0 + 1;
            if (c0 < HW) {
                int kh = c0 / S_DIM, kw = c0 % S_DIM;
                lg[it][0] = acc[0] * scale + Th[r0 * T_STR + qh0 - kh + 13] + Tw[r0 * T_STR + qw0 - kw + 13];
                lg[it][2] = acc[2] * scale + Th[r1 * T_STR + qh1 - kh + 13] + Tw[r1 * T_STR + qw1 - kw + 13];
            } else { lg[it][0] = -1e30f; lg[it][2] = -1e30f; }
            if (c1 < HW) {
                int kh = c1 / S_DIM, kw = c1 % S_DIM;
                lg[it][1] = acc[1] * scale + Th[r0 * T_STR + qh0 - kh + 13] + Tw[r0 * T_STR + qw0 - kw + 13];
                lg[it][3] = acc[3] * scale + Th[r1 * T_STR + qh1 - kh + 13] + Tw[r1 * T_STR + qw1 - kw + 13];
            } else { lg[it][1] = -1e30f; lg[it][3] = -1e30f; }
        }

        float m0 = -1e30f, m1 = -1e30f;
#pragma unroll
        for (int it = 0; it < 13; it++) {
            m0 = fmaxf(m0, fmaxf(lg[it][0], lg[it][1]));
            m1 = fmaxf(m1, fmaxf(lg[it][2], lg[it][3]));
        }
        m0 = fmaxf(m0, __shfl_xor_sync(0xffffffffu, m0, 1));
        m0 = fmaxf(m0, __shfl_xor_sync(0xffffffffu, m0, 2));
        m1 = fmaxf(m1, __shfl_xor_sync(0xffffffffu, m1, 1));
        m1 = fmaxf(m1, __shfl_xor_sync(0xffffffffu, m1, 2));
        if (tig == 0) { redA[wn * 64 + r0] = m0; redA[wn * 64 + r1] = m1; }
        __syncthreads();
        const float M0 = fmaxf(redA[r0], redA[64 + r0]);
        const float M1 = fmaxf(redA[r1], redA[64 + r1]);

        float s0 = 0.f, s1 = 0.f;
#pragma unroll
        for (int it = 0; it < 13; it++) {
            float e0 = __expf(lg[it][0] - M0); lg[it][0] = e0; s0 += e0;
            float e1 = __expf(lg[it][1] - M0); lg[it][1] = e1; s0 += e1;
            float e2 = __expf(lg[it][2] - M1); lg[it][2] = e2; s1 += e2;
            float e3 = __expf(lg[it][3] - M1); lg[it][3] = e3; s1 += e3;
        }
        s0 += __shfl_xor_sync(0xffffffffu, s0, 1);
        s0 += __shfl_xor_sync(0xffffffffu, s0, 2);
        s1 += __shfl_xor_sync(0xffffffffu, s1, 1);
        s1 += __shfl_xor_sync(0xffffffffu, s1, 2);
        if (tig == 0) { redB[wn * 64 + r0] = s0; redB[wn * 64 + r1] = s1; }
        __syncthreads();
        const float inv0 = 1.0f / (redB[r0] + redB[64 + r0]);
        const float inv1 = 1.0f / (redB[r1] + redB[64 + r1]);

        const int row0 = qbase + r0;
        const int row1 = qbase + r1;
        float* atr0 = at_g + ((size_t)bh * HW + row0) * 200;
        float* atr1 = at_g + ((size_t)bh * HW + row1) * 200;
#pragma unroll
        for (int it = 0; it < 13; it++) {
            const int nt = wn * 13 + it;
            const int c0 = nt * 8 + 2 * tig;
            if (c0 < HW) {
                if (row0 < HW) {
                    float2 p = make_float2(f2tf32(lg[it][0] * inv0), f2tf32(lg[it][1] * inv0));
                    *(float2*)(atr0 + c0) = p;
                }
                if (row1 < HW) {
                    float2 p = make_float2(f2tf32(lg[it][2] * inv1), f2tf32(lg[it][3] * inv1));
                    *(float2*)(atr1 + c0) = p;
                }
            }
        }
    }
}

// ---------------------------------------------------------------------------
// Kernel V: out = probs @ V. ctx written fp16 (feeds fp16 proj GEMM).
// ---------------------------------------------------------------------------
#define V_STR  72
#define AT_STR 204
#define V_SMEM_FLOATS (200 * V_STR + 64 * AT_STR)
#define V_SMEM_BYTES  (V_SMEM_FLOATS * 4)

__global__ __launch_bounds__(256, 2)
void attn_av_kernel(const float* __restrict__ qkv,
                    const float* __restrict__ at_g,
                    __half* __restrict__ ctx) {
    extern __shared__ float sm[];
    float* Vs  = sm;
    float* atS = sm + 200 * V_STR;

    const int bh   = blockIdx.x;
    const int b    = bh / NH;
    const int h    = bh % NH;
    const int tid  = threadIdx.x;
    const int warp = tid >> 5;
    const int lane = tid & 31;
    const int g    = lane >> 2;
    const int tig  = lane & 3;
    const int wm   = warp >> 1;
    const int wn   = warp & 1;

    const float* qkv_b = qkv + (size_t)b * HW * QKV_N;
    const float* at_b  = at_g + (size_t)bh * HW * 200;

    for (int slot = tid; slot < 200 * 16; slot += 256) {
        int s  = slot >> 4;
        int d4 = (slot & 15) << 2;
        float4 v = make_float4(0.f, 0.f, 0.f, 0.f);
        if (s < HW) {
            v = *(const float4*)(qkv_b + (size_t)s * QKV_N + 2 * C_DIM + h * HD + d4);
            v.x = f2tf32(v.x); v.y = f2tf32(v.y); v.z = f2tf32(v.z); v.w = f2tf32(v.w);
        }
        *(float4*)&Vs[s * V_STR + d4] = v;
    }

    for (int qb = 0; qb < 4; qb++) {
        const int qbase = qb * 64;
        __syncthreads();

        for (int slot = tid; slot < 64 * 50; slot += 256) {
            int rr = slot / 50;
            int c4 = slot % 50;
            int s  = qbase + rr;
            float4 v = make_float4(0.f, 0.f, 0.f, 0.f);
            if (s < HW && c4 < 49)
                v = *(const float4*)(at_b + (size_t)s * 200 + c4 * 4);
            *(float4*)&atS[rr * AT_STR + c4 * 4] = v;
        }
        __syncthreads();

        const int rB = wm * 16;
        float acc[4][4];
#pragma unroll
        for (int nt = 0; nt < 4; nt++)
#pragma unroll
            for (int i = 0; i < 4; i++) acc[nt][i] = 0.f;

        for (int kc = 0; kc < 25; kc++) {
            const int kb = kc * 8;
            uint32_t a[4];
            a[0] = __float_as_uint(atS[(rB + g    ) * AT_STR + kb + tig    ]);
            a[1] = __float_as_uint(atS[(rB + g + 8) * AT_STR + kb + tig    ]);
            a[2] = __float_as_uint(atS[(rB + g    ) * AT_STR + kb + tig + 4]);
            a[3] = __float_as_uint(atS[(rB + g + 8) * AT_STR + kb + tig + 4]);
#pragma unroll
            for (int nt = 0; nt < 4; nt++) {
                const int col = wn * 32 + nt * 8 + g;
                uint32_t bf[2];
                bf[0] = __float_as_uint(Vs[(kb + tig    ) * V_STR + col]);
                bf[1] = __float_as_uint(Vs[(kb + tig + 4) * V_STR + col]);
                mma_tf32(acc[nt], a, bf);
            }
        }

        const int s0 = qbase + rB + g;
        const int s1 = s0 + 8;
#pragma unroll
        for (int nt = 0; nt < 4; nt++) {
            const int d = wn * 32 + nt * 8 + 2 * tig;
            if (s0 < HW) {
                __half2 p = __floats2half2_rn(acc[nt][0], acc[nt][1]);
                *(__half2*)(ctx + (size_t)(b * HW + s0) * C_DIM + h * HD + d) = p;
            }
            if (s1 < HW) {
                __half2 p = __floats2half2_rn(acc[nt][2], acc[nt][3]);
                *(__half2*)(ctx + (size_t)(b * HW + s1) * C_DIM + h * HD + d) = p;
            }
        }
    }
}

// ---------------------------------------------------------------------------
extern "C" void kernel_launch(void* const* d_in, const int* in_sizes, int n_in,
                              void* d_out, int out_size) {
    const float* x      = (const float*)d_in[0];
    const float* w_qkv  = (const float*)d_in[1];
    const float* b_qkv  = (const float*)d_in[2];
    const float* w_proj = (const float*)d_in[3];
    const float* b_proj = (const float*)d_in[4];
    const float* rph    = (const float*)d_in[5];
    const float* rpw    = (const float*)d_in[6];
    float* out = (float*)d_out;

    float *qkv_ptr, *at_ptr;
    __half *xc, *ctx, *wqT, *wpT;
    cudaGetSymbolAddress((void**)&qkv_ptr, g_qkv);
    cudaGetSymbolAddress((void**)&at_ptr, g_at);
    cudaGetSymbolAddress((void**)&xc, g_xc);
    cudaGetSymbolAddress((void**)&ctx, g_ctx);
    cudaGetSymbolAddress((void**)&wqT, g_wqT);
    cudaGetSymbolAddress((void**)&wpT, g_wpT);

    static bool attr_set = false;
    if (!attr_set) {
        cudaFuncSetAttribute(gemm_f16_bias_t,
                             cudaFuncAttributeMaxDynamicSharedMemorySize,
                             GH_SMEM_BYTES);
        cudaFuncSetAttribute(attn_logits_kernel,
                             cudaFuncAttributeMaxDynamicSharedMemorySize,
                             L_SMEM_BYTES);
        cudaFuncSetAttribute(attn_av_kernel,
                             cudaFuncAttributeMaxDynamicSharedMemorySize,
                             V_SMEM_BYTES);
        attr_set = true;
    }

    // 0) Pre-pass: fp16-convert x; transpose + fp16 weights
    cvt_half_kernel<<<592, 256>>>(x, xc, M_TOK * C_DIM / 4);
    {
        dim3 blk(32, 8);
        dim3 gq(QKV_N / 32, C_DIM / 32);
        transpose_half_kernel<<<gq, blk>>>(w_qkv, wqT, C_DIM, QKV_N);
        dim3 gp(C_DIM / 32, C_DIM / 32);
        transpose_half_kernel<<<gp, blk>>>(w_proj, wpT, C_DIM, C_DIM);
    }

    // 1) QKV projection (fp16 mma m16n8k16, 3-stage pipeline)
    {
        dim3 grid(QKV_N / BNH, (M_TOK + BMH - 1) / BMH);   // 18 x 307
        gemm_f16_bias_t<<<grid, 256, GH_SMEM_BYTES>>>(xc, wqT, b_qkv, qkv_ptr,
                                                      M_TOK, QKV_N, C_DIM);
    }

    // 2a) Logits + bias + softmax -> probs
    attn_logits_kernel<<<NHEADS_TOT, 256, L_SMEM_BYTES>>>(qkv_ptr, rph, rpw, at_ptr);

    // 2b) AV (ctx written fp16)
    attn_av_kernel<<<NHEADS_TOT, 256, V_SMEM_BYTES>>>(qkv_ptr, at_ptr, ctx);

    // 3) Output projection (fp16 mma)
    {
        dim3 grid(C_DIM / BNH, (M_TOK + BMH - 1) / BMH);   // 6 x 307
        gemm_f16_bias_t<<<grid, 256, GH_SMEM_BYTES>>>(ctx, wpT, b_proj, out,
                                                      M_TOK, C_DIM, C_DIM);
    }
}

// round 14
// speedup vs baseline: 1.5038x; 1.0610x over previous
#include <cuda_runtime.h>
#include <cuda_fp16.h>
#include <cstdint>
#include <cstddef>

// Problem constants
#define B_WIN  200
#define S_DIM  14
#define HW     196           // 14*14
#define C_DIM  768
#define NH     12
#define HD     64
#define M_TOK  (B_WIN * HW)  // 39200
#define QKV_N  (3 * C_DIM)   // 2304
#define NHEADS_TOT (B_WIN * NH)   // 2400

// Scratch (device globals: allocation-free per harness rules)
__device__ float  g_qkv[(size_t)M_TOK * QKV_N];          // (B*HW, 2304) fp32
__device__ __half g_at[(size_t)NHEADS_TOT * HW * 200];   // probs fp16, stride 200
__device__ __half g_xc[(size_t)M_TOK * C_DIM];           // x fp16
__device__ __half g_ctx[(size_t)M_TOK * C_DIM];          // ctx fp16
__device__ __half g_wqT[(size_t)QKV_N * C_DIM];          // w_qkv^T [N][K] fp16
__device__ __half g_wpT[(size_t)C_DIM * C_DIM];          // w_proj^T [N][K] fp16

// ---------------------------------------------------------------------------
// helpers
// ---------------------------------------------------------------------------
__device__ __forceinline__ float f2tf32(float x) {
    uint32_t r;
    asm("cvt.rna.tf32.f32 %0, %1;" : "=r"(r) : "f"(x));
    return __uint_as_float(r);
}

__device__ __forceinline__ void mma_tf32(float* c, const uint32_t* a, const uint32_t* b) {
    asm volatile(
        "mma.sync.aligned.m16n8k8.row.col.f32.tf32.tf32.f32 "
        "{%0,%1,%2,%3}, {%4,%5,%6,%7}, {%8,%9}, {%0,%1,%2,%3};"
        : "+f"(c[0]), "+f"(c[1]), "+f"(c[2]), "+f"(c[3])
        : "r"(a[0]), "r"(a[1]), "r"(a[2]), "r"(a[3]),
          "r"(b[0]), "r"(b[1]));
}

__device__ __forceinline__ void mma_f16(float* c, const uint32_t* a, const uint32_t* b) {
    asm volatile(
        "mma.sync.aligned.m16n8k16.row.col.f32.f16.f16.f32 "
        "{%0,%1,%2,%3}, {%4,%5,%6,%7}, {%8,%9}, {%0,%1,%2,%3};"
        : "+f"(c[0]), "+f"(c[1]), "+f"(c[2]), "+f"(c[3])
        : "r"(a[0]), "r"(a[1]), "r"(a[2]), "r"(a[3]),
          "r"(b[0]), "r"(b[1]));
}

__device__ __forceinline__ void ldsm_x4(uint32_t& r0, uint32_t& r1,
                                        uint32_t& r2, uint32_t& r3, uint32_t addr) {
    asm volatile("ldmatrix.sync.aligned.m8n8.x4.shared.b16 {%0,%1,%2,%3}, [%4];"
                 : "=r"(r0), "=r"(r1), "=r"(r2), "=r"(r3) : "r"(addr));
}

// ---------------------------------------------------------------------------
// Pre-pass 1: fp32 -> fp16.
// ---------------------------------------------------------------------------
__global__ void cvt_half_kernel(const float* __restrict__ src,
                                __half* __restrict__ dst, int n4) {
    int i = blockIdx.x * blockDim.x + threadIdx.x;
    int stride = gridDim.x * blockDim.x;
    for (; i < n4; i += stride) {
        float4 v = *(const float4*)(src + (size_t)i * 4);
        __half2 a = __floats2half2_rn(v.x, v.y);
        __half2 b = __floats2half2_rn(v.z, v.w);
        *(__half2*)(dst + (size_t)i * 4)     = a;
        *(__half2*)(dst + (size_t)i * 4 + 2) = b;
    }
}

// ---------------------------------------------------------------------------
// Pre-pass 2: transpose + fp16. src [K][N] fp32 -> dst [N][K] fp16.
// ---------------------------------------------------------------------------
__global__ void transpose_half_kernel(const float* __restrict__ src,
                                      __half* __restrict__ dst, int K, int N) {
    __shared__ float t[32][33];
    const int nb = blockIdx.x * 32;
    const int kb = blockIdx.y * 32;
    const int tx = threadIdx.x, ty = threadIdx.y;
#pragma unroll
    for (int i = 0; i < 32; i += 8)
        t[ty + i][tx] = src[(size_t)(kb + ty + i) * N + nb + tx];
    __syncthreads();
#pragma unroll
    for (int i = 0; i < 32; i += 8)
        dst[(size_t)(nb + ty + i) * K + kb + tx] = __float2half(t[tx][ty + i]);
}

// ---------------------------------------------------------------------------
// fp16 tensor-core GEMM (unchanged from R13).
// ---------------------------------------------------------------------------
#define BMH 128
#define BNH 128
#define BKH 64
#define H_ROWB 144
#define OP_B  (128 * H_ROWB)
#define STAGE_B (2 * OP_B)
#define GH_STAGES 3
#define GH_SMEM_BYTES (GH_STAGES * STAGE_B)   // 110592

__global__ __launch_bounds__(256, 2)
void gemm_f16_bias_t(const __half* __restrict__ X,   // [M][K]
                     const __half* __restrict__ WT,  // [N][K]
                     const float* __restrict__ bias,
                     float* __restrict__ C,
                     int M, int N, int K) {
    extern __shared__ __align__(128) char smg[];
    const uint32_t sbase = (uint32_t)__cvta_generic_to_shared(smg);

    const int tid  = threadIdx.x;
    const int warp = tid >> 5;
    const int lane = tid & 31;
    const int g    = lane >> 2;
    const int tig  = lane & 3;
    const int wtn  = warp >> 1;
    const int wtm  = warp & 1;
    const int m0   = blockIdx.y * BMH;
    const int n0   = blockIdx.x * BNH;

    const int lrA = (lane & 7) + ((lane >> 3) & 1) * 8;
    const int lcA = ((lane >> 4) & 1) * 16;
    const int lrB = (lane & 7) + ((lane >> 4) & 1) * 8;
    const int lcB = ((lane >> 3) & 1) * 16;

    const uint32_t aBase = sbase + OP_B + (uint32_t)((wtn * 32 + lrA) * H_ROWB + lcA);
    const uint32_t bBase = sbase +        (uint32_t)((wtm * 64 + lrB) * H_ROWB + lcB);

    float acc[2][8][4];
#pragma unroll
    for (int i = 0; i < 2; i++)
#pragma unroll
        for (int j = 0; j < 8; j++)
#pragma unroll
            for (int q = 0; q < 4; q++) acc[i][j][q] = 0.f;

    const int T = K / BKH;

    auto stage = [&](int kb, int st) {
        const uint32_t sOff = sbase + (uint32_t)(st * STAGE_B);
        const int kcol = kb * BKH;
#pragma unroll
        for (int i = 0; i < 4; i++) {
            int pos = tid + i * 256;
            int r   = pos >> 3;
            int ch  = pos & 7;
            uint32_t dst = sOff + (uint32_t)(r * H_ROWB + ch * 16);
            const void* src = X + (size_t)(m0 + r) * K + kcol + ch * 8;
            int sz = (m0 + r < M) ? 16 : 0;
            asm volatile("cp.async.cg.shared.global [%0], [%1], 16, %2;\n"
                         :: "r"(dst), "l"(src), "r"(sz));
        }
#pragma unroll
        for (int i = 0; i < 4; i++) {
            int pos = tid + i * 256;
            int r   = pos >> 3;
            int ch  = pos & 7;
            uint32_t dst = sOff + (uint32_t)(OP_B + r * H_ROWB + ch * 16);
            const void* src = WT + (size_t)(n0 + r) * K + kcol + ch * 8;
            asm volatile("cp.async.cg.shared.global [%0], [%1], 16, 16;\n"
                         :: "r"(dst), "l"(src));
        }
        asm volatile("cp.async.commit_group;\n");
    };

    stage(0, 0);
    if (T > 1) stage(1, 1);

    for (int kt = 0; kt < T; kt++) {
        const int st = kt % 3;
        if (kt + 1 < T) asm volatile("cp.async.wait_group 1;\n" ::: "memory");
        else            asm volatile("cp.async.wait_group 0;\n" ::: "memory");
        __syncthreads();
        if (kt + 2 < T) stage(kt + 2, (kt + 2) % 3);

        const uint32_t stOff = (uint32_t)(st * STAGE_B);

#pragma unroll
        for (int kc = 0; kc < 4; kc++) {
            const uint32_t kOff = (uint32_t)(kc * 32);
            uint32_t a[2][4];
#pragma unroll
            for (int i = 0; i < 2; i++)
                ldsm_x4(a[i][0], a[i][1], a[i][2], a[i][3],
                        aBase + stOff + (uint32_t)(i * 16 * H_ROWB) + kOff);
            uint32_t b[8][2];
#pragma unroll
            for (int j2 = 0; j2 < 4; j2++)
                ldsm_x4(b[2 * j2][0], b[2 * j2][1], b[2 * j2 + 1][0], b[2 * j2 + 1][1],
                        bBase + stOff + (uint32_t)(j2 * 16 * H_ROWB) + kOff);
#pragma unroll
            for (int i = 0; i < 2; i++)
#pragma unroll
                for (int j = 0; j < 8; j++)
                    mma_f16(acc[i][j], a[i], b[j]);
        }
    }

#pragma unroll
    for (int i = 0; i < 2; i++) {
        const int na = n0 + wtn * 32 + i * 16 + g;
        const int nb = na + 8;
        const float bva = bias[na];
        const float bvb = bias[nb];
#pragma unroll
        for (int j = 0; j < 8; j++) {
            const int ma = m0 + wtm * 64 + j * 8 + 2 * tig;
            if (ma < M) {
                C[(size_t)ma * N + na] = acc[i][j][0] + bva;
                C[(size_t)ma * N + nb] = acc[i][j][2] + bvb;
            }
            if (ma + 1 < M) {
                C[(size_t)(ma + 1) * N + na] = acc[i][j][1] + bva;
                C[(size_t)(ma + 1) * N + nb] = acc[i][j][3] + bvb;
            }
        }
    }
}

// ---------------------------------------------------------------------------
// Kernel L (fp16 mma): logits + bias + softmax -> probs (fp16 to g_at).
// grid = 2400 (bh). Q/K/rel tables staged as half (stride 72 halves ->
// fragment word banks 4g+tig, conflict-free). K padded to 208 rows (zeros)
// so the discarded nt=25 tile reads zeros. Th/Tw fp32.
// ---------------------------------------------------------------------------
#define QK_H 72      // half stride for KsH/QtH/rel tables

// byte offsets in dynamic smem
#define LB_KS   0                        // half [208][72] = 29952 B
#define LB_QT   29952                    // half [64][72]  = 9216
#define LB_RPH  39168                    // half [32][72]  = 4608
#define LB_RPW  43776                    // half [32][72]  = 4608
#define LB_TH   48384                    // float [64][36] = 9216
#define LB_TW   57600                    // float [64][36] = 9216
#define LB_REDA 66816                    // float [2][64]  = 512
#define LB_REDB 67328                    // float [2][64]  = 512
#define LB_QHW  67840                    // int [128]      = 512
#define L_SMEM_BYTES 68352

__global__ __launch_bounds__(256, 2)
void attn_logits_kernel(const float* __restrict__ qkv,
                        const float* __restrict__ rph,
                        const float* __restrict__ rpw,
                        __half* __restrict__ at_g) {
    extern __shared__ __align__(16) char smc[];
    __half* KsH  = (__half*)(smc + LB_KS);
    __half* QtH  = (__half*)(smc + LB_QT);
    __half* rphS = (__half*)(smc + LB_RPH);
    __half* rpwS = (__half*)(smc + LB_RPW);
    float*  Th   = (float*)(smc + LB_TH);
    float*  Tw   = (float*)(smc + LB_TW);
    float*  redA = (float*)(smc + LB_REDA);
    float*  redB = (float*)(smc + LB_REDB);
    int*    qhw  = (int*)(smc + LB_QHW);

    const int bh   = blockIdx.x;
    const int b    = bh / NH;
    const int h    = bh % NH;
    const int tid  = threadIdx.x;
    const int warp = tid >> 5;
    const int lane = tid & 31;
    const int g    = lane >> 2;
    const int tig  = lane & 3;
    const int wm   = warp >> 1;
    const int wn   = warp & 1;
    const float scale = 0.125f;

    const float* qkv_b = qkv + (size_t)b * HW * QKV_N;

    // rel tables as half [32][72], rows 27..31 zero (natural [j][d] layout)
    for (int slot = tid; slot < 32 * 16; slot += 256) {
        int j  = slot >> 4;
        int d4 = (slot & 15) << 2;
        float4 vh = make_float4(0.f, 0.f, 0.f, 0.f);
        float4 vw = make_float4(0.f, 0.f, 0.f, 0.f);
        if (j < 2 * S_DIM - 1) {
            vh = *(const float4*)(rph + (size_t)j * HD + d4);
            vw = *(const float4*)(rpw + (size_t)j * HD + d4);
        }
        *(__half2*)&rphS[j * QK_H + d4]     = __floats2half2_rn(vh.x, vh.y);
        *(__half2*)&rphS[j * QK_H + d4 + 2] = __floats2half2_rn(vh.z, vh.w);
        *(__half2*)&rpwS[j * QK_H + d4]     = __floats2half2_rn(vw.x, vw.y);
        *(__half2*)&rpwS[j * QK_H + d4 + 2] = __floats2half2_rn(vw.z, vw.w);
    }
    // K as half [208][72], rows 196..207 zero
    for (int slot = tid; slot < 208 * 16; slot += 256) {
        int s  = slot >> 4;
        int d4 = (slot & 15) << 2;
        float4 v = make_float4(0.f, 0.f, 0.f, 0.f);
        if (s < HW)
            v = *(const float4*)(qkv_b + (size_t)s * QKV_N + C_DIM + h * HD + d4);
        *(__half2*)&KsH[s * QK_H + d4]     = __floats2half2_rn(v.x, v.y);
        *(__half2*)&KsH[s * QK_H + d4 + 2] = __floats2half2_rn(v.z, v.w);
    }

    for (int qb = 0; qb < 4; qb++) {
        const int qbase = qb * 64;
        __syncthreads();

        // Q block as half
        for (int slot = tid; slot < 64 * 16; slot += 256) {
            int ql = slot >> 4;
            int d4 = (slot & 15) << 2;
            int s  = qbase + ql;
            float4 v = make_float4(0.f, 0.f, 0.f, 0.f);
            if (s < HW)
                v = *(const float4*)(qkv_b + (size_t)s * QKV_N + h * HD + d4);
            *(__half2*)&QtH[ql * QK_H + d4]     = __floats2half2_rn(v.x, v.y);
            *(__half2*)&QtH[ql * QK_H + d4 + 2] = __floats2half2_rn(v.z, v.w);
        }
        if (tid < 64) {
            int s = qbase + tid;
            qhw[tid]      = s / S_DIM;
            qhw[64 + tid] = s % S_DIM;
        }
        __syncthreads();

        // hoist Q fragments: 4 k16-chunks
        const int rB = wm * 16;
        uint32_t af[4][4];
#pragma unroll
        for (int kc = 0; kc < 4; kc++) {
            const int kb = kc * 16 + 2 * tig;
            af[kc][0] = *(const uint32_t*)&QtH[(rB + g    ) * QK_H + kb    ];
            af[kc][1] = *(const uint32_t*)&QtH[(rB + g + 8) * QK_H + kb    ];
            af[kc][2] = *(const uint32_t*)&QtH[(rB + g    ) * QK_H + kb + 8];
            af[kc][3] = *(const uint32_t*)&QtH[(rB + g + 8) * QK_H + kb + 8];
        }

        // T-mma: wn=0 -> Th from rphS ; wn=1 -> Tw from rpwS
        {
            const __half* Bt = wn ? rpwS : rphS;
            float*        Dt = wn ? Tw   : Th;
#pragma unroll
            for (int nt = 0; nt < 4; nt++) {
                float acc[4] = {0.f, 0.f, 0.f, 0.f};
                const int col = nt * 8 + g;
#pragma unroll
                for (int kc = 0; kc < 4; kc++) {
                    const int kb = kc * 16 + 2 * tig;
                    uint32_t bf[2];
                    bf[0] = *(const uint32_t*)&Bt[col * QK_H + kb    ];
                    bf[1] = *(const uint32_t*)&Bt[col * QK_H + kb + 8];
                    mma_f16(acc, af[kc], bf);
                }
                const int c0 = nt * 8 + 2 * tig;
                Dt[(rB + g    ) * 36 + c0    ] = acc[0];
                Dt[(rB + g    ) * 36 + c0 + 1] = acc[1];
                Dt[(rB + g + 8) * 36 + c0    ] = acc[2];
                Dt[(rB + g + 8) * 36 + c0 + 1] = acc[3];
            }
        }
        __syncthreads();

        // QK^T: 13 n-tiles per warp
        const int r0 = rB + g;
        const int r1 = r0 + 8;
        const int qh0 = qhw[r0],      qw0 = qhw[64 + r0];
        const int qh1 = qhw[r1],      qw1 = qhw[64 + r1];
        float lg[13][4];
#pragma unroll
        for (int it = 0; it < 13; it++) {
            const int nt  = wn * 13 + it;
            float acc[4] = {0.f, 0.f, 0.f, 0.f};
            const int col = nt * 8 + g;     // <= 207, rows zeroed past 195
#pragma unroll
            for (int kc = 0; kc < 4; kc++) {
                const int kb = kc * 16 + 2 * tig;
                uint32_t bf[2];
                bf[0] = *(const uint32_t*)&KsH[col * QK_H + kb    ];
                bf[1] = *(const uint32_t*)&KsH[col * QK_H + kb + 8];
                mma_f16(acc, af[kc], bf);
            }
            const int c0 = nt * 8 + 2 * tig;
            const int c1 = c0 + 1;
            if (c0 < HW) {
                int kh = c0 / S_DIM, kw = c0 % S_DIM;
                lg[it][0] = acc[0] * scale + Th[r0 * 36 + qh0 - kh + 13] + Tw[r0 * 36 + qw0 - kw + 13];
                lg[it][2] = acc[2] * scale + Th[r1 * 36 + qh1 - kh + 13] + Tw[r1 * 36 + qw1 - kw + 13];
            } else { lg[it][0] = -1e30f; lg[it][2] = -1e30f; }
            if (c1 < HW) {
                int kh = c1 / S_DIM, kw = c1 % S_DIM;
                lg[it][1] = acc[1] * scale + Th[r0 * 36 + qh0 - kh + 13] + Tw[r0 * 36 + qw0 - kw + 13];
                lg[it][3] = acc[3] * scale + Th[r1 * 36 + qh1 - kh + 13] + Tw[r1 * 36 + qw1 - kw + 13];
            } else { lg[it][1] = -1e30f; lg[it][3] = -1e30f; }
        }

        // softmax (row max / exp / sum; cross-warp via smem)
        float m0 = -1e30f, m1 = -1e30f;
#pragma unroll
        for (int it = 0; it < 13; it++) {
            m0 = fmaxf(m0, fmaxf(lg[it][0], lg[it][1]));
            m1 = fmaxf(m1, fmaxf(lg[it][2], lg[it][3]));
        }
        m0 = fmaxf(m0, __shfl_xor_sync(0xffffffffu, m0, 1));
        m0 = fmaxf(m0, __shfl_xor_sync(0xffffffffu, m0, 2));
        m1 = fmaxf(m1, __shfl_xor_sync(0xffffffffu, m1, 1));
        m1 = fmaxf(m1, __shfl_xor_sync(0xffffffffu, m1, 2));
        if (tig == 0) { redA[wn * 64 + r0] = m0; redA[wn * 64 + r1] = m1; }
        __syncthreads();
        const float M0 = fmaxf(redA[r0], redA[64 + r0]);
        const float M1 = fmaxf(redA[r1], redA[64 + r1]);

        float s0 = 0.f, s1 = 0.f;
#pragma unroll
        for (int it = 0; it < 13; it++) {
            float e0 = __expf(lg[it][0] - M0); lg[it][0] = e0; s0 += e0;
            float e1 = __expf(lg[it][1] - M0); lg[it][1] = e1; s0 += e1;
            float e2 = __expf(lg[it][2] - M1); lg[it][2] = e2; s1 += e2;
            float e3 = __expf(lg[it][3] - M1); lg[it][3] = e3; s1 += e3;
        }
        s0 += __shfl_xor_sync(0xffffffffu, s0, 1);
        s0 += __shfl_xor_sync(0xffffffffu, s0, 2);
        s1 += __shfl_xor_sync(0xffffffffu, s1, 1);
        s1 += __shfl_xor_sync(0xffffffffu, s1, 2);
        if (tig == 0) { redB[wn * 64 + r0] = s0; redB[wn * 64 + r1] = s1; }
        __syncthreads();
        const float inv0 = 1.0f / (redB[r0] + redB[64 + r0]);
        const float inv1 = 1.0f / (redB[r1] + redB[64 + r1]);

        // write probs fp16
        const int row0 = qbase + r0;
        const int row1 = qbase + r1;
        __half* atr0 = at_g + ((size_t)bh * HW + row0) * 200;
        __half* atr1 = at_g + ((size_t)bh * HW + row1) * 200;
#pragma unroll
        for (int it = 0; it < 13; it++) {
            const int nt = wn * 13 + it;
            const int c0 = nt * 8 + 2 * tig;
            if (c0 < HW) {
                if (row0 < HW)
                    *(__half2*)(atr0 + c0) = __floats2half2_rn(lg[it][0] * inv0, lg[it][1] * inv0);
                if (row1 < HW)
                    *(__half2*)(atr1 + c0) = __floats2half2_rn(lg[it][2] * inv1, lg[it][3] * inv1);
            }
        }
    }
}

// ---------------------------------------------------------------------------
// Kernel V: out = probs @ V (tf32 mma, unchanged math). Reads fp16 probs
// (exact in tf32), writes ctx fp16.
// ---------------------------------------------------------------------------
#define V_STR  72
#define AT_STR 204
#define V_SMEM_FLOATS (200 * V_STR + 64 * AT_STR)
#define V_SMEM_BYTES  (V_SMEM_FLOATS * 4)

__global__ __launch_bounds__(256, 2)
void attn_av_kernel(const float* __restrict__ qkv,
                    const __half* __restrict__ at_g,
                    __half* __restrict__ ctx) {
    extern __shared__ float sm[];
    float* Vs  = sm;
    float* atS = sm + 200 * V_STR;

    const int bh   = blockIdx.x;
    const int b    = bh / NH;
    const int h    = bh % NH;
    const int tid  = threadIdx.x;
    const int warp = tid >> 5;
    const int lane = tid & 31;
    const int g    = lane >> 2;
    const int tig  = lane & 3;
    const int wm   = warp >> 1;
    const int wn   = warp & 1;

    const float* qkv_b = qkv + (size_t)b * HW * QKV_N;
    const __half* at_b = at_g + (size_t)bh * HW * 200;

    for (int slot = tid; slot < 200 * 16; slot += 256) {
        int s  = slot >> 4;
        int d4 = (slot & 15) << 2;
        float4 v = make_float4(0.f, 0.f, 0.f, 0.f);
        if (s < HW) {
            v = *(const float4*)(qkv_b + (size_t)s * QKV_N + 2 * C_DIM + h * HD + d4);
            v.x = f2tf32(v.x); v.y = f2tf32(v.y); v.z = f2tf32(v.z); v.w = f2tf32(v.w);
        }
        *(float4*)&Vs[s * V_STR + d4] = v;
    }

    for (int qb = 0; qb < 4; qb++) {
        const int qbase = qb * 64;
        __syncthreads();

        for (int slot = tid; slot < 64 * 50; slot += 256) {
            int rr = slot / 50;
            int c4 = slot % 50;
            int s  = qbase + rr;
            float4 v = make_float4(0.f, 0.f, 0.f, 0.f);
            if (s < HW && c4 < 49) {
                __half2 p0 = *(const __half2*)(at_b + (size_t)s * 200 + c4 * 4);
                __half2 p1 = *(const __half2*)(at_b + (size_t)s * 200 + c4 * 4 + 2);
                v.x = __low2float(p0);  v.y = __high2float(p0);
                v.z = __low2float(p1);  v.w = __high2float(p1);
            }
            *(float4*)&atS[rr * AT_STR + c4 * 4] = v;
        }
        __syncthreads();

        const int rB = wm * 16;
        float acc[4][4];
#pragma unroll
        for (int nt = 0; nt < 4; nt++)
#pragma unroll
            for (int i = 0; i < 4; i++) acc[nt][i] = 0.f;

        for (int kc = 0; kc < 25; kc++) {
            const int kb = kc * 8;
            uint32_t a[4];
            a[0] = __float_as_uint(atS[(rB + g    ) * AT_STR + kb + tig    ]);
            a[1] = __float_as_uint(atS[(rB + g + 8) * AT_STR + kb + tig    ]);
            a[2] = __float_as_uint(atS[(rB + g    ) * AT_STR + kb + tig + 4]);
            a[3] = __float_as_uint(atS[(rB + g + 8) * AT_STR + kb + tig + 4]);
#pragma unroll
            for (int nt = 0; nt < 4; nt++) {
                const int col = wn * 32 + nt * 8 + g;
                uint32_t bf[2];
                bf[0] = __float_as_uint(Vs[(kb + tig    ) * V_STR + col]);
                bf[1] = __float_as_uint(Vs[(kb + tig + 4) * V_STR + col]);
                mma_tf32(acc[nt], a, bf);
            }
        }

        const int s0 = qbase + rB + g;
        const int s1 = s0 + 8;
#pragma unroll
        for (int nt = 0; nt < 4; nt++) {
            const int d = wn * 32 + nt * 8 + 2 * tig;
            if (s0 < HW) {
                __half2 p = __floats2half2_rn(acc[nt][0], acc[nt][1]);
                *(__half2*)(ctx + (size_t)(b * HW + s0) * C_DIM + h * HD + d) = p;
            }
            if (s1 < HW) {
                __half2 p = __floats2half2_rn(acc[nt][2], acc[nt][3]);
                *(__half2*)(ctx + (size_t)(b * HW + s1) * C_DIM + h * HD + d) = p;
            }
        }
    }
}

// ---------------------------------------------------------------------------
extern "C" void kernel_launch(void* const* d_in, const int* in_sizes, int n_in,
                              void* d_out, int out_size) {
    const float* x      = (const float*)d_in[0];
    const float* w_qkv  = (const float*)d_in[1];
    const float* b_qkv  = (const float*)d_in[2];
    const float* w_proj = (const float*)d_in[3];
    const float* b_proj = (const float*)d_in[4];
    const float* rph    = (const float*)d_in[5];
    const float* rpw    = (const float*)d_in[6];
    float* out = (float*)d_out;

    float *qkv_ptr;
    __half *at_ptr, *xc, *ctx, *wqT, *wpT;
    cudaGetSymbolAddress((void**)&qkv_ptr, g_qkv);
    cudaGetSymbolAddress((void**)&at_ptr, g_at);
    cudaGetSymbolAddress((void**)&xc, g_xc);
    cudaGetSymbolAddress((void**)&ctx, g_ctx);
    cudaGetSymbolAddress((void**)&wqT, g_wqT);
    cudaGetSymbolAddress((void**)&wpT, g_wpT);

    static bool attr_set = false;
    if (!attr_set) {
        cudaFuncSetAttribute(gemm_f16_bias_t,
                             cudaFuncAttributeMaxDynamicSharedMemorySize,
                             GH_SMEM_BYTES);
        cudaFuncSetAttribute(attn_logits_kernel,
                             cudaFuncAttributeMaxDynamicSharedMemorySize,
                             L_SMEM_BYTES);
        cudaFuncSetAttribute(attn_av_kernel,
                             cudaFuncAttributeMaxDynamicSharedMemorySize,
                             V_SMEM_BYTES);
        attr_set = true;
    }

    // 0) Pre-pass: fp16-convert x; transpose + fp16 weights
    cvt_half_kernel<<<592, 256>>>(x, xc, M_TOK * C_DIM / 4);
    {
        dim3 blk(32, 8);
        dim3 gq(QKV_N / 32, C_DIM / 32);
        transpose_half_kernel<<<gq, blk>>>(w_qkv, wqT, C_DIM, QKV_N);
        dim3 gp(C_DIM / 32, C_DIM / 32);
        transpose_half_kernel<<<gp, blk>>>(w_proj, wpT, C_DIM, C_DIM);
    }

    // 1) QKV projection (fp16 mma)
    {
        dim3 grid(QKV_N / BNH, (M_TOK + BMH - 1) / BMH);   // 18 x 307
        gemm_f16_bias_t<<<grid, 256, GH_SMEM_BYTES>>>(xc, wqT, b_qkv, qkv_ptr,
                                                      M_TOK, QKV_N, C_DIM);
    }

    // 2a) Logits + bias + softmax -> probs (fp16 mma; probs fp16)
    attn_logits_kernel<<<NHEADS_TOT, 256, L_SMEM_BYTES>>>(qkv_ptr, rph, rpw, at_ptr);

    // 2b) AV (tf32 mma; reads fp16 probs; ctx fp16)
    attn_av_kernel<<<NHEADS_TOT, 256, V_SMEM_BYTES>>>(qkv_ptr, at_ptr, ctx);

    // 3) Output projection (fp16 mma)
    {
        dim3 grid(C_DIM / BNH, (M_TOK + BMH - 1) / BMH);   // 6 x 307
        gemm_f16_bias_t<<<grid, 256, GH_SMEM_BYTES>>>(ctx, wpT, b_proj, out,
                                                      M_TOK, C_DIM, C_DIM);
    }
}

// round 15
// speedup vs baseline: 1.6539x; 1.0998x over previous
#include <cuda_runtime.h>
#include <cuda_fp16.h>
#include <cstdint>
#include <cstddef>

// Problem constants
#define B_WIN  200
#define S_DIM  14
#define HW     196           // 14*14
#define C_DIM  768
#define NH     12
#define HD     64
#define M_TOK  (B_WIN * HW)  // 39200
#define QKV_N  (3 * C_DIM)   // 2304
#define NHEADS_TOT (B_WIN * NH)   // 2400

// Scratch (device globals: allocation-free per harness rules)
__device__ __half g_qkvh[(size_t)M_TOK * QKV_N];         // qkv fp16
__device__ __half g_at[(size_t)NHEADS_TOT * HW * 200];   // probs fp16, stride 200
__device__ __half g_xc[(size_t)M_TOK * C_DIM];           // x fp16
__device__ __half g_ctx[(size_t)M_TOK * C_DIM];          // ctx fp16
__device__ __half g_wqT[(size_t)QKV_N * C_DIM];          // w_qkv^T [N][K] fp16
__device__ __half g_wpT[(size_t)C_DIM * C_DIM];          // w_proj^T [N][K] fp16

// ---------------------------------------------------------------------------
// helpers
// ---------------------------------------------------------------------------
__device__ __forceinline__ void mma_f16(float* c, const uint32_t* a, const uint32_t* b) {
    asm volatile(
        "mma.sync.aligned.m16n8k16.row.col.f32.f16.f16.f32 "
        "{%0,%1,%2,%3}, {%4,%5,%6,%7}, {%8,%9}, {%0,%1,%2,%3};"
        : "+f"(c[0]), "+f"(c[1]), "+f"(c[2]), "+f"(c[3])
        : "r"(a[0]), "r"(a[1]), "r"(a[2]), "r"(a[3]),
          "r"(b[0]), "r"(b[1]));
}

__device__ __forceinline__ void ldsm_x4(uint32_t& r0, uint32_t& r1,
                                        uint32_t& r2, uint32_t& r3, uint32_t addr) {
    asm volatile("ldmatrix.sync.aligned.m8n8.x4.shared.b16 {%0,%1,%2,%3}, [%4];"
                 : "=r"(r0), "=r"(r1), "=r"(r2), "=r"(r3) : "r"(addr));
}

// ---------------------------------------------------------------------------
// Pre-pass 1: fp32 -> fp16.
// ---------------------------------------------------------------------------
__global__ void cvt_half_kernel(const float* __restrict__ src,
                                __half* __restrict__ dst, int n4) {
    int i = blockIdx.x * blockDim.x + threadIdx.x;
    int stride = gridDim.x * blockDim.x;
    for (; i < n4; i += stride) {
        float4 v = *(const float4*)(src + (size_t)i * 4);
        __half2 a = __floats2half2_rn(v.x, v.y);
        __half2 b = __floats2half2_rn(v.z, v.w);
        *(__half2*)(dst + (size_t)i * 4)     = a;
        *(__half2*)(dst + (size_t)i * 4 + 2) = b;
    }
}

// ---------------------------------------------------------------------------
// Pre-pass 2: transpose + fp16. src [K][N] fp32 -> dst [N][K] fp16.
// ---------------------------------------------------------------------------
__global__ void transpose_half_kernel(const float* __restrict__ src,
                                      __half* __restrict__ dst, int K, int N) {
    __shared__ float t[32][33];
    const int nb = blockIdx.x * 32;
    const int kb = blockIdx.y * 32;
    const int tx = threadIdx.x, ty = threadIdx.y;
#pragma unroll
    for (int i = 0; i < 32; i += 8)
        t[ty + i][tx] = src[(size_t)(kb + ty + i) * N + nb + tx];
    __syncthreads();
#pragma unroll
    for (int i = 0; i < 32; i += 8)
        dst[(size_t)(nb + ty + i) * K + kb + tx] = __float2half(t[tx][ty + i]);
}

// ---------------------------------------------------------------------------
// fp16 tensor-core GEMM (templated output type).
// ---------------------------------------------------------------------------
#define BMH 128
#define BNH 128
#define BKH 64
#define H_ROWB 144
#define OP_B  (128 * H_ROWB)
#define STAGE_B (2 * OP_B)
#define GH_STAGES 3
#define GH_SMEM_BYTES (GH_STAGES * STAGE_B)   // 110592

template <typename OutT>
__global__ __launch_bounds__(256, 2)
void gemm_f16_bias_t(const __half* __restrict__ X,   // [M][K]
                     const __half* __restrict__ WT,  // [N][K]
                     const float* __restrict__ bias,
                     OutT* __restrict__ C,
                     int M, int N, int K) {
    extern __shared__ __align__(128) char smg[];
    const uint32_t sbase = (uint32_t)__cvta_generic_to_shared(smg);

    const int tid  = threadIdx.x;
    const int warp = tid >> 5;
    const int lane = tid & 31;
    const int g    = lane >> 2;
    const int tig  = lane & 3;
    const int wtn  = warp >> 1;
    const int wtm  = warp & 1;
    const int m0   = blockIdx.y * BMH;
    const int n0   = blockIdx.x * BNH;

    const int lrA = (lane & 7) + ((lane >> 3) & 1) * 8;
    const int lcA = ((lane >> 4) & 1) * 16;
    const int lrB = (lane & 7) + ((lane >> 4) & 1) * 8;
    const int lcB = ((lane >> 3) & 1) * 16;

    const uint32_t aBase = sbase + OP_B + (uint32_t)((wtn * 32 + lrA) * H_ROWB + lcA);
    const uint32_t bBase = sbase +        (uint32_t)((wtm * 64 + lrB) * H_ROWB + lcB);

    float acc[2][8][4];
#pragma unroll
    for (int i = 0; i < 2; i++)
#pragma unroll
        for (int j = 0; j < 8; j++)
#pragma unroll
            for (int q = 0; q < 4; q++) acc[i][j][q] = 0.f;

    const int T = K / BKH;

    auto stage = [&](int kb, int st) {
        const uint32_t sOff = sbase + (uint32_t)(st * STAGE_B);
        const int kcol = kb * BKH;
#pragma unroll
        for (int i = 0; i < 4; i++) {
            int pos = tid + i * 256;
            int r   = pos >> 3;
            int ch  = pos & 7;
            uint32_t dst = sOff + (uint32_t)(r * H_ROWB + ch * 16);
            const void* src = X + (size_t)(m0 + r) * K + kcol + ch * 8;
            int sz = (m0 + r < M) ? 16 : 0;
            asm volatile("cp.async.cg.shared.global [%0], [%1], 16, %2;\n"
                         :: "r"(dst), "l"(src), "r"(sz));
        }
#pragma unroll
        for (int i = 0; i < 4; i++) {
            int pos = tid + i * 256;
            int r   = pos >> 3;
            int ch  = pos & 7;
            uint32_t dst = sOff + (uint32_t)(OP_B + r * H_ROWB + ch * 16);
            const void* src = WT + (size_t)(n0 + r) * K + kcol + ch * 8;
            asm volatile("cp.async.cg.shared.global [%0], [%1], 16, 16;\n"
                         :: "r"(dst), "l"(src));
        }
        asm volatile("cp.async.commit_group;\n");
    };

    stage(0, 0);
    if (T > 1) stage(1, 1);

    for (int kt = 0; kt < T; kt++) {
        const int st = kt % 3;
        if (kt + 1 < T) asm volatile("cp.async.wait_group 1;\n" ::: "memory");
        else            asm volatile("cp.async.wait_group 0;\n" ::: "memory");
        __syncthreads();
        if (kt + 2 < T) stage(kt + 2, (kt + 2) % 3);

        const uint32_t stOff = (uint32_t)(st * STAGE_B);

#pragma unroll
        for (int kc = 0; kc < 4; kc++) {
            const uint32_t kOff = (uint32_t)(kc * 32);
            uint32_t a[2][4];
#pragma unroll
            for (int i = 0; i < 2; i++)
                ldsm_x4(a[i][0], a[i][1], a[i][2], a[i][3],
                        aBase + stOff + (uint32_t)(i * 16 * H_ROWB) + kOff);
            uint32_t b[8][2];
#pragma unroll
            for (int j2 = 0; j2 < 4; j2++)
                ldsm_x4(b[2 * j2][0], b[2 * j2][1], b[2 * j2 + 1][0], b[2 * j2 + 1][1],
                        bBase + stOff + (uint32_t)(j2 * 16 * H_ROWB) + kOff);
#pragma unroll
            for (int i = 0; i < 2; i++)
#pragma unroll
                for (int j = 0; j < 8; j++)
                    mma_f16(acc[i][j], a[i], b[j]);
        }
    }

#pragma unroll
    for (int i = 0; i < 2; i++) {
        const int na = n0 + wtn * 32 + i * 16 + g;
        const int nb = na + 8;
        const float bva = bias[na];
        const float bvb = bias[nb];
#pragma unroll
        for (int j = 0; j < 8; j++) {
            const int ma = m0 + wtm * 64 + j * 8 + 2 * tig;
            if (ma < M) {
                if constexpr (sizeof(OutT) == 2) {
                    C[(size_t)ma * N + na] = __float2half(acc[i][j][0] + bva);
                    C[(size_t)ma * N + nb] = __float2half(acc[i][j][2] + bvb);
                } else {
                    C[(size_t)ma * N + na] = acc[i][j][0] + bva;
                    C[(size_t)ma * N + nb] = acc[i][j][2] + bvb;
                }
            }
            if (ma + 1 < M) {
                if constexpr (sizeof(OutT) == 2) {
                    C[(size_t)(ma + 1) * N + na] = __float2half(acc[i][j][1] + bva);
                    C[(size_t)(ma + 1) * N + nb] = __float2half(acc[i][j][3] + bvb);
                } else {
                    C[(size_t)(ma + 1) * N + na] = acc[i][j][1] + bva;
                    C[(size_t)(ma + 1) * N + nb] = acc[i][j][3] + bvb;
                }
            }
        }
    }
}

// ---------------------------------------------------------------------------
// Kernel L (fp16 mma): logits + bias + softmax -> probs fp16.
// qkv now fp16: staging is plain uint4 copies. Probs cols 196..199 zeroed.
// ---------------------------------------------------------------------------
#define QK_H 72

#define LB_KS   0                        // half [208][72] = 29952 B
#define LB_QT   29952                    // half [64][72]  = 9216
#define LB_RPH  39168                    // half [32][72]  = 4608
#define LB_RPW  43776                    // half [32][72]  = 4608
#define LB_TH   48384                    // float [64][36] = 9216
#define LB_TW   57600                    // float [64][36] = 9216
#define LB_REDA 66816
#define LB_REDB 67328
#define LB_QHW  67840
#define L_SMEM_BYTES 68352

__global__ __launch_bounds__(256, 2)
void attn_logits_kernel(const __half* __restrict__ qkv,
                        const float* __restrict__ rph,
                        const float* __restrict__ rpw,
                        __half* __restrict__ at_g) {
    extern __shared__ __align__(16) char smc[];
    __half* KsH  = (__half*)(smc + LB_KS);
    __half* QtH  = (__half*)(smc + LB_QT);
    __half* rphS = (__half*)(smc + LB_RPH);
    __half* rpwS = (__half*)(smc + LB_RPW);
    float*  Th   = (float*)(smc + LB_TH);
    float*  Tw   = (float*)(smc + LB_TW);
    float*  redA = (float*)(smc + LB_REDA);
    float*  redB = (float*)(smc + LB_REDB);
    int*    qhw  = (int*)(smc + LB_QHW);

    const int bh   = blockIdx.x;
    const int b    = bh / NH;
    const int h    = bh % NH;
    const int tid  = threadIdx.x;
    const int warp = tid >> 5;
    const int lane = tid & 31;
    const int g    = lane >> 2;
    const int tig  = lane & 3;
    const int wm   = warp >> 1;
    const int wn   = warp & 1;
    const float scale = 0.125f;

    const __half* qkv_b = qkv + (size_t)b * HW * QKV_N;

    // rel tables as half [32][72], rows 27..31 zero
    for (int slot = tid; slot < 32 * 16; slot += 256) {
        int j  = slot >> 4;
        int d4 = (slot & 15) << 2;
        float4 vh = make_float4(0.f, 0.f, 0.f, 0.f);
        float4 vw = make_float4(0.f, 0.f, 0.f, 0.f);
        if (j < 2 * S_DIM - 1) {
            vh = *(const float4*)(rph + (size_t)j * HD + d4);
            vw = *(const float4*)(rpw + (size_t)j * HD + d4);
        }
        *(__half2*)&rphS[j * QK_H + d4]     = __floats2half2_rn(vh.x, vh.y);
        *(__half2*)&rphS[j * QK_H + d4 + 2] = __floats2half2_rn(vh.z, vh.w);
        *(__half2*)&rpwS[j * QK_H + d4]     = __floats2half2_rn(vw.x, vw.y);
        *(__half2*)&rpwS[j * QK_H + d4 + 2] = __floats2half2_rn(vw.z, vw.w);
    }
    // K: [208][72] half, rows 196..207 zero; plain uint4 copies
    for (int slot = tid; slot < 208 * 8; slot += 256) {
        int s  = slot >> 3;
        int c8 = (slot & 7) * 8;
        uint4 v = make_uint4(0u, 0u, 0u, 0u);
        if (s < HW)
            v = *(const uint4*)(qkv_b + (size_t)s * QKV_N + C_DIM + h * HD + c8);
        *(uint4*)&KsH[s * QK_H + c8] = v;
    }

    for (int qb = 0; qb < 4; qb++) {
        const int qbase = qb * 64;
        __syncthreads();

        for (int slot = tid; slot < 64 * 8; slot += 256) {
            int ql = slot >> 3;
            int c8 = (slot & 7) * 8;
            int s  = qbase + ql;
            uint4 v = make_uint4(0u, 0u, 0u, 0u);
            if (s < HW)
                v = *(const uint4*)(qkv_b + (size_t)s * QKV_N + h * HD + c8);
            *(uint4*)&QtH[ql * QK_H + c8] = v;
        }
        if (tid < 64) {
            int s = qbase + tid;
            qhw[tid]      = s / S_DIM;
            qhw[64 + tid] = s % S_DIM;
        }
        __syncthreads();

        const int rB = wm * 16;
        uint32_t af[4][4];
#pragma unroll
        for (int kc = 0; kc < 4; kc++) {
            const int kb = kc * 16 + 2 * tig;
            af[kc][0] = *(const uint32_t*)&QtH[(rB + g    ) * QK_H + kb    ];
            af[kc][1] = *(const uint32_t*)&QtH[(rB + g + 8) * QK_H + kb    ];
            af[kc][2] = *(const uint32_t*)&QtH[(rB + g    ) * QK_H + kb + 8];
            af[kc][3] = *(const uint32_t*)&QtH[(rB + g + 8) * QK_H + kb + 8];
        }

        {
            const __half* Bt = wn ? rpwS : rphS;
            float*        Dt = wn ? Tw   : Th;
#pragma unroll
            for (int nt = 0; nt < 4; nt++) {
                float acc[4] = {0.f, 0.f, 0.f, 0.f};
                const int col = nt * 8 + g;
#pragma unroll
                for (int kc = 0; kc < 4; kc++) {
                    const int kb = kc * 16 + 2 * tig;
                    uint32_t bf[2];
                    bf[0] = *(const uint32_t*)&Bt[col * QK_H + kb    ];
                    bf[1] = *(const uint32_t*)&Bt[col * QK_H + kb + 8];
                    mma_f16(acc, af[kc], bf);
                }
                const int c0 = nt * 8 + 2 * tig;
                Dt[(rB + g    ) * 36 + c0    ] = acc[0];
                Dt[(rB + g    ) * 36 + c0 + 1] = acc[1];
                Dt[(rB + g + 8) * 36 + c0    ] = acc[2];
                Dt[(rB + g + 8) * 36 + c0 + 1] = acc[3];
            }
        }
        __syncthreads();

        const int r0 = rB + g;
        const int r1 = r0 + 8;
        const int qh0 = qhw[r0],      qw0 = qhw[64 + r0];
        const int qh1 = qhw[r1],      qw1 = qhw[64 + r1];
        float lg[13][4];
#pragma unroll
        for (int it = 0; it < 13; it++) {
            const int nt  = wn * 13 + it;
            float acc[4] = {0.f, 0.f, 0.f, 0.f};
            const int col = nt * 8 + g;
#pragma unroll
            for (int kc = 0; kc < 4; kc++) {
                const int kb = kc * 16 + 2 * tig;
                uint32_t bf[2];
                bf[0] = *(const uint32_t*)&KsH[col * QK_H + kb    ];
                bf[1] = *(const uint32_t*)&KsH[col * QK_H + kb + 8];
                mma_f16(acc, af[kc], bf);
            }
            const int c0 = nt * 8 + 2 * tig;
            const int c1 = c0 + 1;
            if (c0 < HW) {
                int kh = c0 / S_DIM, kw = c0 % S_DIM;
                lg[it][0] = acc[0] * scale + Th[r0 * 36 + qh0 - kh + 13] + Tw[r0 * 36 + qw0 - kw + 13];
                lg[it][2] = acc[2] * scale + Th[r1 * 36 + qh1 - kh + 13] + Tw[r1 * 36 + qw1 - kw + 13];
            } else { lg[it][0] = -1e30f; lg[it][2] = -1e30f; }
            if (c1 < HW) {
                int kh = c1 / S_DIM, kw = c1 % S_DIM;
                lg[it][1] = acc[1] * scale + Th[r0 * 36 + qh0 - kh + 13] + Tw[r0 * 36 + qw0 - kw + 13];
                lg[it][3] = acc[3] * scale + Th[r1 * 36 + qh1 - kh + 13] + Tw[r1 * 36 + qw1 - kw + 13];
            } else { lg[it][1] = -1e30f; lg[it][3] = -1e30f; }
        }

        float m0 = -1e30f, m1 = -1e30f;
#pragma unroll
        for (int it = 0; it < 13; it++) {
            m0 = fmaxf(m0, fmaxf(lg[it][0], lg[it][1]));
            m1 = fmaxf(m1, fmaxf(lg[it][2], lg[it][3]));
        }
        m0 = fmaxf(m0, __shfl_xor_sync(0xffffffffu, m0, 1));
        m0 = fmaxf(m0, __shfl_xor_sync(0xffffffffu, m0, 2));
        m1 = fmaxf(m1, __shfl_xor_sync(0xffffffffu, m1, 1));
        m1 = fmaxf(m1, __shfl_xor_sync(0xffffffffu, m1, 2));
        if (tig == 0) { redA[wn * 64 + r0] = m0; redA[wn * 64 + r1] = m1; }
        __syncthreads();
        const float M0 = fmaxf(redA[r0], redA[64 + r0]);
        const float M1 = fmaxf(redA[r1], redA[64 + r1]);

        float s0 = 0.f, s1 = 0.f;
#pragma unroll
        for (int it = 0; it < 13; it++) {
            float e0 = __expf(lg[it][0] - M0); lg[it][0] = e0; s0 += e0;
            float e1 = __expf(lg[it][1] - M0); lg[it][1] = e1; s0 += e1;
            float e2 = __expf(lg[it][2] - M1); lg[it][2] = e2; s1 += e2;
            float e3 = __expf(lg[it][3] - M1); lg[it][3] = e3; s1 += e3;
        }
        s0 += __shfl_xor_sync(0xffffffffu, s0, 1);
        s0 += __shfl_xor_sync(0xffffffffu, s0, 2);
        s1 += __shfl_xor_sync(0xffffffffu, s1, 1);
        s1 += __shfl_xor_sync(0xffffffffu, s1, 2);
        if (tig == 0) { redB[wn * 64 + r0] = s0; redB[wn * 64 + r1] = s1; }
        __syncthreads();
        const float inv0 = 1.0f / (redB[r0] + redB[64 + r0]);
        const float inv1 = 1.0f / (redB[r1] + redB[64 + r1]);

        const int row0 = qbase + r0;
        const int row1 = qbase + r1;
        __half* atr0 = at_g + ((size_t)bh * HW + row0) * 200;
        __half* atr1 = at_g + ((size_t)bh * HW + row1) * 200;
#pragma unroll
        for (int it = 0; it < 13; it++) {
            const int nt = wn * 13 + it;
            const int c0 = nt * 8 + 2 * tig;
            if (c0 < HW) {
                if (row0 < HW)
                    *(__half2*)(atr0 + c0) = __floats2half2_rn(lg[it][0] * inv0, lg[it][1] * inv0);
                if (row1 < HW)
                    *(__half2*)(atr1 + c0) = __floats2half2_rn(lg[it][2] * inv1, lg[it][3] * inv1);
            }
        }
        // zero-pad probs cols 196..199 (consumed in 16B chunks by AV kernel)
        if (wn == 0 && tig == 0) {
            __half2 z = __floats2half2_rn(0.f, 0.f);
            if (row0 < HW) { *(__half2*)(atr0 + 196) = z; *(__half2*)(atr0 + 198) = z; }
            if (row1 < HW) { *(__half2*)(atr1 + 196) = z; *(__half2*)(atr1 + 198) = z; }
        }
    }
}

// ---------------------------------------------------------------------------
// Kernel V (fp16 mma): out = probs @ V via transposed-operand scheme.
// A = V^T [64 d][208 k], B = P [64 q][208 k], D = (d x q). Stride 216 halves
// (432B): ldmatrix phase banks 12r+{0..3} tile all 32 banks (conflict-free).
// ---------------------------------------------------------------------------
#define VT_STR 216
#define AV_VT_B (64 * VT_STR * 2)          // 27648
#define AV_SMEM_BYTES (2 * AV_VT_B)        // 55296

__global__ __launch_bounds__(256, 2)
void attn_av_kernel(const __half* __restrict__ qkv,
                    const __half* __restrict__ at_g,
                    __half* __restrict__ ctx) {
    extern __shared__ __align__(16) char smv[];
    __half* Vt = (__half*)smv;                 // [64][216]
    __half* Pt = (__half*)(smv + AV_VT_B);     // [64][216]
    const uint32_t sbase = (uint32_t)__cvta_generic_to_shared(smv);

    const int bh   = blockIdx.x;
    const int b    = bh / NH;
    const int h    = bh % NH;
    const int tid  = threadIdx.x;
    const int warp = tid >> 5;
    const int lane = tid & 31;
    const int g    = lane >> 2;
    const int tig  = lane & 3;
    const int wtn  = warp >> 1;    // 0..3 : d-tile (16)
    const int wtm  = warp & 1;     // 0..1 : q-half (32)

    const __half* qkv_b = qkv + (size_t)b * HW * QKV_N;
    const __half* at_b  = at_g + (size_t)bh * HW * 200;

    // Stage V transposed: Vt[d][s], cols s>=196 zero (read 8 d per thread)
    for (int slot = tid; slot < 208 * 8; slot += 256) {
        int s  = slot >> 3;
        int d8 = (slot & 7) * 8;
        if (s < HW) {
            uint4 v = *(const uint4*)(qkv_b + (size_t)s * QKV_N + 2 * C_DIM + h * HD + d8);
            const __half* hv = (const __half*)&v;
#pragma unroll
            for (int i = 0; i < 8; i++) Vt[(d8 + i) * VT_STR + s] = hv[i];
        } else {
#pragma unroll
            for (int i = 0; i < 8; i++) Vt[(d8 + i) * VT_STR + s] = __float2half(0.f);
        }
    }

    // ldmatrix lane coords (same scheme as GEMM)
    const int lrA = (lane & 7) + ((lane >> 3) & 1) * 8;
    const int lcA = ((lane >> 4) & 1) * 16;
    const int lrB = (lane & 7) + ((lane >> 4) & 1) * 8;
    const int lcB = ((lane >> 3) & 1) * 16;
    const uint32_t aBase = sbase + (uint32_t)((wtn * 16 + lrA) * (VT_STR * 2) + lcA);
    const uint32_t bBase = sbase + (uint32_t)AV_VT_B
                         + (uint32_t)((wtm * 32 + lrB) * (VT_STR * 2) + lcB);

    for (int qb = 0; qb < 4; qb++) {
        const int qbase = qb * 64;
        __syncthreads();   // Vt (first iter) / previous Pt consumers done

        // Stage probs tile: [64 q][208 k], 26 uint4 chunks per row
        for (int slot = tid; slot < 64 * 26; slot += 256) {
            int rr = slot / 26;
            int c8 = (slot % 26) * 8;
            int s  = qbase + rr;
            uint4 v = make_uint4(0u, 0u, 0u, 0u);
            if (s < HW && c8 < 200)
                v = *(const uint4*)(at_b + (size_t)s * 200 + c8);
            *(uint4*)&Pt[rr * VT_STR + c8] = v;
        }
        __syncthreads();

        float acc[4][4];
#pragma unroll
        for (int j = 0; j < 4; j++)
#pragma unroll
            for (int q = 0; q < 4; q++) acc[j][q] = 0.f;

#pragma unroll
        for (int kc = 0; kc < 13; kc++) {
            const uint32_t kOff = (uint32_t)(kc * 32);
            uint32_t a[4];
            ldsm_x4(a[0], a[1], a[2], a[3], aBase + kOff);
            uint32_t bb[4][2];
#pragma unroll
            for (int j2 = 0; j2 < 2; j2++)
                ldsm_x4(bb[2 * j2][0], bb[2 * j2][1], bb[2 * j2 + 1][0], bb[2 * j2 + 1][1],
                        bBase + (uint32_t)(j2 * 16 * VT_STR * 2) + kOff);
#pragma unroll
            for (int j = 0; j < 4; j++)
                mma_f16(acc[j], a, bb[j]);
        }

        // D(n=d x m=q): c0=(d0,q0), c1=(d0,q0+1), c2=(d0+8,q0), c3=(d0+8,q0+1)
        const int d0 = wtn * 16 + g;
        const int d1 = d0 + 8;
#pragma unroll
        for (int j = 0; j < 4; j++) {
            const int q0 = qbase + wtm * 32 + j * 8 + 2 * tig;
#pragma unroll
            for (int dq = 0; dq < 2; dq++) {
                const int q = q0 + dq;
                if (q < HW) {
                    __half* dst = ctx + (size_t)(b * HW + q) * C_DIM + h * HD;
                    dst[d0] = __float2half(acc[j][dq]);
                    dst[d1] = __float2half(acc[j][2 + dq]);
                }
            }
        }
    }
}

// ---------------------------------------------------------------------------
extern "C" void kernel_launch(void* const* d_in, const int* in_sizes, int n_in,
                              void* d_out, int out_size) {
    const float* x      = (const float*)d_in[0];
    const float* w_qkv  = (const float*)d_in[1];
    const float* b_qkv  = (const float*)d_in[2];
    const float* w_proj = (const float*)d_in[3];
    const float* b_proj = (const float*)d_in[4];
    const float* rph    = (const float*)d_in[5];
    const float* rpw    = (const float*)d_in[6];
    float* out = (float*)d_out;

    __half *qkvh, *at_ptr, *xc, *ctx, *wqT, *wpT;
    cudaGetSymbolAddress((void**)&qkvh, g_qkvh);
    cudaGetSymbolAddress((void**)&at_ptr, g_at);
    cudaGetSymbolAddress((void**)&xc, g_xc);
    cudaGetSymbolAddress((void**)&ctx, g_ctx);
    cudaGetSymbolAddress((void**)&wqT, g_wqT);
    cudaGetSymbolAddress((void**)&wpT, g_wpT);

    static bool attr_set = false;
    if (!attr_set) {
        cudaFuncSetAttribute(gemm_f16_bias_t<__half>,
                             cudaFuncAttributeMaxDynamicSharedMemorySize,
                             GH_SMEM_BYTES);
        cudaFuncSetAttribute(gemm_f16_bias_t<float>,
                             cudaFuncAttributeMaxDynamicSharedMemorySize,
                             GH_SMEM_BYTES);
        cudaFuncSetAttribute(attn_logits_kernel,
                             cudaFuncAttributeMaxDynamicSharedMemorySize,
                             L_SMEM_BYTES);
        cudaFuncSetAttribute(attn_av_kernel,
                             cudaFuncAttributeMaxDynamicSharedMemorySize,
                             AV_SMEM_BYTES);
        attr_set = true;
    }

    // 0) Pre-pass: fp16-convert x; transpose + fp16 weights
    cvt_half_kernel<<<592, 256>>>(x, xc, M_TOK * C_DIM / 4);
    {
        dim3 blk(32, 8);
        dim3 gq(QKV_N / 32, C_DIM / 32);
        transpose_half_kernel<<<gq, blk>>>(w_qkv, wqT, C_DIM, QKV_N);
        dim3 gp(C_DIM / 32, C_DIM / 32);
        transpose_half_kernel<<<gp, blk>>>(w_proj, wpT, C_DIM, C_DIM);
    }

    // 1) QKV projection (fp16 mma, fp16 output)
    {
        dim3 grid(QKV_N / BNH, (M_TOK + BMH - 1) / BMH);   // 18 x 307
        gemm_f16_bias_t<__half><<<grid, 256, GH_SMEM_BYTES>>>(xc, wqT, b_qkv, qkvh,
                                                              M_TOK, QKV_N, C_DIM);
    }

    // 2a) Logits + bias + softmax -> probs fp16
    attn_logits_kernel<<<NHEADS_TOT, 256, L_SMEM_BYTES>>>(qkvh, rph, rpw, at_ptr);

    // 2b) AV (fp16 mma; ctx fp16)
    attn_av_kernel<<<NHEADS_TOT, 256, AV_SMEM_BYTES>>>(qkvh, at_ptr, ctx);

    // 3) Output projection (fp16 mma, fp32 output)
    {
        dim3 grid(C_DIM / BNH, (M_TOK + BMH - 1) / BMH);   // 6 x 307
        gemm_f16_bias_t<float><<<grid, 256, GH_SMEM_BYTES>>>(ctx, wpT, b_proj, out,
                                                             M_TOK, C_DIM, C_DIM);
    }
}

// round 16
// speedup vs baseline: 1.8083x; 1.0933x over previous
#include <cuda_runtime.h>
#include <cuda_fp16.h>
#include <cstdint>
#include <cstddef>

// Problem constants
#define B_WIN  200
#define S_DIM  14
#define HW     196           // 14*14
#define C_DIM  768
#define NH     12
#define HD     64
#define M_TOK  (B_WIN * HW)  // 39200
#define QKV_N  (3 * C_DIM)   // 2304
#define NHEADS_TOT (B_WIN * NH)   // 2400

// Scratch (device globals: allocation-free per harness rules)
__device__ __half g_qkvh[(size_t)M_TOK * QKV_N];         // qkv fp16
__device__ __half g_xc[(size_t)M_TOK * C_DIM];           // x fp16
__device__ __half g_ctx[(size_t)M_TOK * C_DIM];          // ctx fp16
__device__ __half g_wqT[(size_t)QKV_N * C_DIM];          // w_qkv^T [N][K] fp16
__device__ __half g_wpT[(size_t)C_DIM * C_DIM];          // w_proj^T [N][K] fp16

// ---------------------------------------------------------------------------
// helpers
// ---------------------------------------------------------------------------
__device__ __forceinline__ void mma_f16(float* c, const uint32_t* a, const uint32_t* b) {
    asm volatile(
        "mma.sync.aligned.m16n8k16.row.col.f32.f16.f16.f32 "
        "{%0,%1,%2,%3}, {%4,%5,%6,%7}, {%8,%9}, {%0,%1,%2,%3};"
        : "+f"(c[0]), "+f"(c[1]), "+f"(c[2]), "+f"(c[3])
        : "r"(a[0]), "r"(a[1]), "r"(a[2]), "r"(a[3]),
          "r"(b[0]), "r"(b[1]));
}

__device__ __forceinline__ void ldsm_x4(uint32_t& r0, uint32_t& r1,
                                        uint32_t& r2, uint32_t& r3, uint32_t addr) {
    asm volatile("ldmatrix.sync.aligned.m8n8.x4.shared.b16 {%0,%1,%2,%3}, [%4];"
                 : "=r"(r0), "=r"(r1), "=r"(r2), "=r"(r3) : "r"(addr));
}

__device__ __forceinline__ uint32_t packh2(float lo, float hi) {
    __half2 h = __floats2half2_rn(lo, hi);
    return *(uint32_t*)&h;
}

// ---------------------------------------------------------------------------
// Pre-pass 1: fp32 -> fp16.
// ---------------------------------------------------------------------------
__global__ void cvt_half_kernel(const float* __restrict__ src,
                                __half* __restrict__ dst, int n4) {
    int i = blockIdx.x * blockDim.x + threadIdx.x;
    int stride = gridDim.x * blockDim.x;
    for (; i < n4; i += stride) {
        float4 v = *(const float4*)(src + (size_t)i * 4);
        __half2 a = __floats2half2_rn(v.x, v.y);
        __half2 b = __floats2half2_rn(v.z, v.w);
        *(__half2*)(dst + (size_t)i * 4)     = a;
        *(__half2*)(dst + (size_t)i * 4 + 2) = b;
    }
}

// ---------------------------------------------------------------------------
// Pre-pass 2: transpose + fp16. src [K][N] fp32 -> dst [N][K] fp16.
// ---------------------------------------------------------------------------
__global__ void transpose_half_kernel(const float* __restrict__ src,
                                      __half* __restrict__ dst, int K, int N) {
    __shared__ float t[32][33];
    const int nb = blockIdx.x * 32;
    const int kb = blockIdx.y * 32;
    const int tx = threadIdx.x, ty = threadIdx.y;
#pragma unroll
    for (int i = 0; i < 32; i += 8)
        t[ty + i][tx] = src[(size_t)(kb + ty + i) * N + nb + tx];
    __syncthreads();
#pragma unroll
    for (int i = 0; i < 32; i += 8)
        dst[(size_t)(nb + ty + i) * K + kb + tx] = __float2half(t[tx][ty + i]);
}

// ---------------------------------------------------------------------------
// fp16 tensor-core GEMM (unchanged from R15).
// ---------------------------------------------------------------------------
#define BMH 128
#define BNH 128
#define BKH 64
#define H_ROWB 144
#define OP_B  (128 * H_ROWB)
#define STAGE_B (2 * OP_B)
#define GH_STAGES 3
#define GH_SMEM_BYTES (GH_STAGES * STAGE_B)   // 110592

template <typename OutT>
__global__ __launch_bounds__(256, 2)
void gemm_f16_bias_t(const __half* __restrict__ X,   // [M][K]
                     const __half* __restrict__ WT,  // [N][K]
                     const float* __restrict__ bias,
                     OutT* __restrict__ C,
                     int M, int N, int K) {
    extern __shared__ __align__(128) char smg[];
    const uint32_t sbase = (uint32_t)__cvta_generic_to_shared(smg);

    const int tid  = threadIdx.x;
    const int warp = tid >> 5;
    const int lane = tid & 31;
    const int g    = lane >> 2;
    const int tig  = lane & 3;
    const int wtn  = warp >> 1;
    const int wtm  = warp & 1;
    const int m0   = blockIdx.y * BMH;
    const int n0   = blockIdx.x * BNH;

    const int lrA = (lane & 7) + ((lane >> 3) & 1) * 8;
    const int lcA = ((lane >> 4) & 1) * 16;
    const int lrB = (lane & 7) + ((lane >> 4) & 1) * 8;
    const int lcB = ((lane >> 3) & 1) * 16;

    const uint32_t aBase = sbase + OP_B + (uint32_t)((wtn * 32 + lrA) * H_ROWB + lcA);
    const uint32_t bBase = sbase +        (uint32_t)((wtm * 64 + lrB) * H_ROWB + lcB);

    float acc[2][8][4];
#pragma unroll
    for (int i = 0; i < 2; i++)
#pragma unroll
        for (int j = 0; j < 8; j++)
#pragma unroll
            for (int q = 0; q < 4; q++) acc[i][j][q] = 0.f;

    const int T = K / BKH;

    auto stage = [&](int kb, int st) {
        const uint32_t sOff = sbase + (uint32_t)(st * STAGE_B);
        const int kcol = kb * BKH;
#pragma unroll
        for (int i = 0; i < 4; i++) {
            int pos = tid + i * 256;
            int r   = pos >> 3;
            int ch  = pos & 7;
            uint32_t dst = sOff + (uint32_t)(r * H_ROWB + ch * 16);
            const void* src = X + (size_t)(m0 + r) * K + kcol + ch * 8;
            int sz = (m0 + r < M) ? 16 : 0;
            asm volatile("cp.async.cg.shared.global [%0], [%1], 16, %2;\n"
                         :: "r"(dst), "l"(src), "r"(sz));
        }
#pragma unroll
        for (int i = 0; i < 4; i++) {
            int pos = tid + i * 256;
            int r   = pos >> 3;
            int ch  = pos & 7;
            uint32_t dst = sOff + (uint32_t)(OP_B + r * H_ROWB + ch * 16);
            const void* src = WT + (size_t)(n0 + r) * K + kcol + ch * 8;
            asm volatile("cp.async.cg.shared.global [%0], [%1], 16, 16;\n"
                         :: "r"(dst), "l"(src));
        }
        asm volatile("cp.async.commit_group;\n");
    };

    stage(0, 0);
    if (T > 1) stage(1, 1);

    for (int kt = 0; kt < T; kt++) {
        const int st = kt % 3;
        if (kt + 1 < T) asm volatile("cp.async.wait_group 1;\n" ::: "memory");
        else            asm volatile("cp.async.wait_group 0;\n" ::: "memory");
        __syncthreads();
        if (kt + 2 < T) stage(kt + 2, (kt + 2) % 3);

        const uint32_t stOff = (uint32_t)(st * STAGE_B);

#pragma unroll
        for (int kc = 0; kc < 4; kc++) {
            const uint32_t kOff = (uint32_t)(kc * 32);
            uint32_t a[2][4];
#pragma unroll
            for (int i = 0; i < 2; i++)
                ldsm_x4(a[i][0], a[i][1], a[i][2], a[i][3],
                        aBase + stOff + (uint32_t)(i * 16 * H_ROWB) + kOff);
            uint32_t b[8][2];
#pragma unroll
            for (int j2 = 0; j2 < 4; j2++)
                ldsm_x4(b[2 * j2][0], b[2 * j2][1], b[2 * j2 + 1][0], b[2 * j2 + 1][1],
                        bBase + stOff + (uint32_t)(j2 * 16 * H_ROWB) + kOff);
#pragma unroll
            for (int i = 0; i < 2; i++)
#pragma unroll
                for (int j = 0; j < 8; j++)
                    mma_f16(acc[i][j], a[i], b[j]);
        }
    }

#pragma unroll
    for (int i = 0; i < 2; i++) {
        const int na = n0 + wtn * 32 + i * 16 + g;
        const int nb = na + 8;
        const float bva = bias[na];
        const float bvb = bias[nb];
#pragma unroll
        for (int j = 0; j < 8; j++) {
            const int ma = m0 + wtm * 64 + j * 8 + 2 * tig;
            if (ma < M) {
                if constexpr (sizeof(OutT) == 2) {
                    C[(size_t)ma * N + na] = __float2half(acc[i][j][0] + bva);
                    C[(size_t)ma * N + nb] = __float2half(acc[i][j][2] + bvb);
                } else {
                    C[(size_t)ma * N + na] = acc[i][j][0] + bva;
                    C[(size_t)ma * N + nb] = acc[i][j][2] + bvb;
                }
            }
            if (ma + 1 < M) {
                if constexpr (sizeof(OutT) == 2) {
                    C[(size_t)(ma + 1) * N + na] = __float2half(acc[i][j][1] + bva);
                    C[(size_t)(ma + 1) * N + nb] = __float2half(acc[i][j][3] + bvb);
                } else {
                    C[(size_t)(ma + 1) * N + na] = acc[i][j][1] + bva;
                    C[(size_t)(ma + 1) * N + nb] = acc[i][j][3] + bvb;
                }
            }
        }
    }
}

// ---------------------------------------------------------------------------
// Fused attention kernel: logits + bias + softmax + AV, probs stay in
// registers (B-fragments built by packing). grid = 2400 (bh), 256 threads.
// ---------------------------------------------------------------------------
#define QK_H  72
#define VT_S  216   // Vt half stride (432B rows -> ldsm conflict-free)

#define FB_KS   0                        // half [208][72] = 29952
#define FB_VT   29952                    // half [64][216] = 27648
#define FB_QT   57600                    // half [64][72]  = 9216
#define FB_RPH  66816                    // half [32][72]  = 4608
#define FB_RPW  71424                    // half [32][72]  = 4608
#define FB_TH   76032                    // float [64][36] = 9216  (aliased: partial)
#define FB_TW   85248                    // float [64][36] = 9216  (alias cont.)
#define FB_REDA 94464                    // float [2][64]
#define FB_REDB 94976
#define FB_QHW  95488                    // int [128]
#define F_SMEM_BYTES 96000

__global__ __launch_bounds__(256, 2)
void attn_fused_kernel(const __half* __restrict__ qkv,
                       const float* __restrict__ rph,
                       const float* __restrict__ rpw,
                       __half* __restrict__ ctx) {
    extern __shared__ __align__(16) char smc[];
    __half* KsH  = (__half*)(smc + FB_KS);
    __half* Vt   = (__half*)(smc + FB_VT);
    __half* QtH  = (__half*)(smc + FB_QT);
    __half* rphS = (__half*)(smc + FB_RPH);
    __half* rpwS = (__half*)(smc + FB_RPW);
    float*  Th   = (float*)(smc + FB_TH);
    float*  Tw   = (float*)(smc + FB_TW);
    float*  part = (float*)(smc + FB_TH);   // alias: [4 wm][64 d][17]
    float*  redA = (float*)(smc + FB_REDA);
    float*  redB = (float*)(smc + FB_REDB);
    int*    qhw  = (int*)(smc + FB_QHW);
    const uint32_t sbase = (uint32_t)__cvta_generic_to_shared(smc);

    const int bh   = blockIdx.x;
    const int b    = bh / NH;
    const int h    = bh % NH;
    const int tid  = threadIdx.x;
    const int warp = tid >> 5;
    const int lane = tid & 31;
    const int g    = lane >> 2;
    const int tig  = lane & 3;
    const int wm   = warp >> 1;
    const int wn   = warp & 1;
    const float scale = 0.125f;

    const __half* qkv_b = qkv + (size_t)b * HW * QKV_N;

    // rel tables as half [32][72], rows 27..31 zero
    for (int slot = tid; slot < 32 * 16; slot += 256) {
        int j  = slot >> 4;
        int d4 = (slot & 15) << 2;
        float4 vh = make_float4(0.f, 0.f, 0.f, 0.f);
        float4 vw = make_float4(0.f, 0.f, 0.f, 0.f);
        if (j < 2 * S_DIM - 1) {
            vh = *(const float4*)(rph + (size_t)j * HD + d4);
            vw = *(const float4*)(rpw + (size_t)j * HD + d4);
        }
        *(__half2*)&rphS[j * QK_H + d4]     = __floats2half2_rn(vh.x, vh.y);
        *(__half2*)&rphS[j * QK_H + d4 + 2] = __floats2half2_rn(vh.z, vh.w);
        *(__half2*)&rpwS[j * QK_H + d4]     = __floats2half2_rn(vw.x, vw.y);
        *(__half2*)&rpwS[j * QK_H + d4 + 2] = __floats2half2_rn(vw.z, vw.w);
    }
    // K: [208][72] half, rows 196..207 zero
    for (int slot = tid; slot < 208 * 8; slot += 256) {
        int s  = slot >> 3;
        int c8 = (slot & 7) * 8;
        uint4 v = make_uint4(0u, 0u, 0u, 0u);
        if (s < HW)
            v = *(const uint4*)(qkv_b + (size_t)s * QKV_N + C_DIM + h * HD + c8);
        *(uint4*)&KsH[s * QK_H + c8] = v;
    }
    // V transposed: Vt[d][s], s cols 196..207 zero
    {
        const __half zh = __float2half(0.f);
        for (int slot = tid; slot < 208 * 8; slot += 256) {
            int s  = slot >> 3;
            int d8 = (slot & 7) * 8;
            if (s < HW) {
                uint4 v = *(const uint4*)(qkv_b + (size_t)s * QKV_N + 2 * C_DIM + h * HD + d8);
                const __half* hv = (const __half*)&v;
#pragma unroll
                for (int i = 0; i < 8; i++) Vt[(d8 + i) * VT_S + s] = hv[i];
            } else {
#pragma unroll
                for (int i = 0; i < 8; i++) Vt[(d8 + i) * VT_S + s] = zh;
            }
        }
        // zero cols 208..215 (read by overhung ldsm, multiplied by 0)
        for (int slot = tid; slot < 64 * 8; slot += 256) {
            int d = slot >> 3;
            int c = 208 + (slot & 7);
            Vt[d * VT_S + c] = zh;
        }
    }

    // ldsm lane coords for Vt (A operand)
    const int lrA = (lane & 7) + ((lane >> 3) & 1) * 8;
    const int lcA = ((lane >> 4) & 1) * 16;
    const uint32_t vtBase = sbase + FB_VT + (uint32_t)(lrA * (VT_S * 2) + lcA);

    for (int qb = 0; qb < 4; qb++) {
        const int qbase = qb * 64;
        __syncthreads();   // staging (first iter) / part + Qt reuse

        // Q block
        for (int slot = tid; slot < 64 * 8; slot += 256) {
            int ql = slot >> 3;
            int c8 = (slot & 7) * 8;
            int s  = qbase + ql;
            uint4 v = make_uint4(0u, 0u, 0u, 0u);
            if (s < HW)
                v = *(const uint4*)(qkv_b + (size_t)s * QKV_N + h * HD + c8);
            *(uint4*)&QtH[ql * QK_H + c8] = v;
        }
        if (tid < 64) {
            int s = qbase + tid;
            qhw[tid]      = s / S_DIM;
            qhw[64 + tid] = s % S_DIM;
        }
        __syncthreads();

        const int rB = wm * 16;
        uint32_t af[4][4];
#pragma unroll
        for (int kc = 0; kc < 4; kc++) {
            const int kb = kc * 16 + 2 * tig;
            af[kc][0] = *(const uint32_t*)&QtH[(rB + g    ) * QK_H + kb    ];
            af[kc][1] = *(const uint32_t*)&QtH[(rB + g + 8) * QK_H + kb    ];
            af[kc][2] = *(const uint32_t*)&QtH[(rB + g    ) * QK_H + kb + 8];
            af[kc][3] = *(const uint32_t*)&QtH[(rB + g + 8) * QK_H + kb + 8];
        }

        // T-mma: wn=0 -> Th ; wn=1 -> Tw
        {
            const __half* Bt = wn ? rpwS : rphS;
            float*        Dt = wn ? Tw   : Th;
#pragma unroll
            for (int nt = 0; nt < 4; nt++) {
                float acc[4] = {0.f, 0.f, 0.f, 0.f};
                const int col = nt * 8 + g;
#pragma unroll
                for (int kc = 0; kc < 4; kc++) {
                    const int kb = kc * 16 + 2 * tig;
                    uint32_t bf[2];
                    bf[0] = *(const uint32_t*)&Bt[col * QK_H + kb    ];
                    bf[1] = *(const uint32_t*)&Bt[col * QK_H + kb + 8];
                    mma_f16(acc, af[kc], bf);
                }
                const int c0 = nt * 8 + 2 * tig;
                Dt[(rB + g    ) * 36 + c0    ] = acc[0];
                Dt[(rB + g    ) * 36 + c0 + 1] = acc[1];
                Dt[(rB + g + 8) * 36 + c0    ] = acc[2];
                Dt[(rB + g + 8) * 36 + c0 + 1] = acc[3];
            }
        }
        __syncthreads();

        // QK^T: 13 n-tiles per warp (logits in registers)
        const int r0 = rB + g;
        const int r1 = r0 + 8;
        const int qh0 = qhw[r0],      qw0 = qhw[64 + r0];
        const int qh1 = qhw[r1],      qw1 = qhw[64 + r1];
        float lg[13][4];
#pragma unroll
        for (int it = 0; it < 13; it++) {
            const int nt  = wn * 13 + it;
            float acc[4] = {0.f, 0.f, 0.f, 0.f};
            const int col = nt * 8 + g;
#pragma unroll
            for (int kc = 0; kc < 4; kc++) {
                const int kb = kc * 16 + 2 * tig;
                uint32_t bf[2];
                bf[0] = *(const uint32_t*)&KsH[col * QK_H + kb    ];
                bf[1] = *(const uint32_t*)&KsH[col * QK_H + kb + 8];
                mma_f16(acc, af[kc], bf);
            }
            const int c0 = nt * 8 + 2 * tig;
            const int c1 = c0 + 1;
            if (c0 < HW) {
                int kh = c0 / S_DIM, kw = c0 % S_DIM;
                lg[it][0] = acc[0] * scale + Th[r0 * 36 + qh0 - kh + 13] + Tw[r0 * 36 + qw0 - kw + 13];
                lg[it][2] = acc[2] * scale + Th[r1 * 36 + qh1 - kh + 13] + Tw[r1 * 36 + qw1 - kw + 13];
            } else { lg[it][0] = -1e30f; lg[it][2] = -1e30f; }
            if (c1 < HW) {
                int kh = c1 / S_DIM, kw = c1 % S_DIM;
                lg[it][1] = acc[1] * scale + Th[r0 * 36 + qh0 - kh + 13] + Tw[r0 * 36 + qw0 - kw + 13];
                lg[it][3] = acc[3] * scale + Th[r1 * 36 + qh1 - kh + 13] + Tw[r1 * 36 + qw1 - kw + 13];
            } else { lg[it][1] = -1e30f; lg[it][3] = -1e30f; }
        }

        // softmax
        float m0 = -1e30f, m1 = -1e30f;
#pragma unroll
        for (int it = 0; it < 13; it++) {
            m0 = fmaxf(m0, fmaxf(lg[it][0], lg[it][1]));
            m1 = fmaxf(m1, fmaxf(lg[it][2], lg[it][3]));
        }
        m0 = fmaxf(m0, __shfl_xor_sync(0xffffffffu, m0, 1));
        m0 = fmaxf(m0, __shfl_xor_sync(0xffffffffu, m0, 2));
        m1 = fmaxf(m1, __shfl_xor_sync(0xffffffffu, m1, 1));
        m1 = fmaxf(m1, __shfl_xor_sync(0xffffffffu, m1, 2));
        if (tig == 0) { redA[wn * 64 + r0] = m0; redA[wn * 64 + r1] = m1; }
        __syncthreads();
        const float M0 = fmaxf(redA[r0], redA[64 + r0]);
        const float M1 = fmaxf(redA[r1], redA[64 + r1]);

        float s0 = 0.f, s1 = 0.f;
#pragma unroll
        for (int it = 0; it < 13; it++) {
            float e0 = __expf(lg[it][0] - M0); lg[it][0] = e0; s0 += e0;
            float e1 = __expf(lg[it][1] - M0); lg[it][1] = e1; s0 += e1;
            float e2 = __expf(lg[it][2] - M1); lg[it][2] = e2; s1 += e2;
            float e3 = __expf(lg[it][3] - M1); lg[it][3] = e3; s1 += e3;
        }
        s0 += __shfl_xor_sync(0xffffffffu, s0, 1);
        s0 += __shfl_xor_sync(0xffffffffu, s0, 2);
        s1 += __shfl_xor_sync(0xffffffffu, s1, 1);
        s1 += __shfl_xor_sync(0xffffffffu, s1, 2);
        if (tig == 0) { redB[wn * 64 + r0] = s0; redB[wn * 64 + r1] = s1; }
        __syncthreads();
        const float inv0 = 1.0f / (redB[r0] + redB[64 + r0]);
        const float inv1 = 1.0f / (redB[r1] + redB[64 + r1]);

        // ---- AV: probs packed from registers as B-fragments ----
        float av[4][2][4];
#pragma unroll
        for (int dt = 0; dt < 4; dt++)
#pragma unroll
            for (int qg = 0; qg < 2; qg++)
#pragma unroll
                for (int q = 0; q < 4; q++) av[dt][qg][q] = 0.f;

#pragma unroll
        for (int j = 0; j < 7; j++) {
            const uint32_t kOrgB = (uint32_t)(((wn * 13 + 2 * j) * 8) * 2);  // bytes
            uint32_t bq0[2], bq1[2];
            bq0[0] = packh2(lg[2 * j][0] * inv0, lg[2 * j][1] * inv0);
            bq1[0] = packh2(lg[2 * j][2] * inv1, lg[2 * j][3] * inv1);
            if (j < 6) {
                bq0[1] = packh2(lg[2 * j + 1][0] * inv0, lg[2 * j + 1][1] * inv0);
                bq1[1] = packh2(lg[2 * j + 1][2] * inv1, lg[2 * j + 1][3] * inv1);
            } else {
                bq0[1] = 0u; bq1[1] = 0u;
            }
#pragma unroll
            for (int dt = 0; dt < 4; dt++) {
                uint32_t a[4];
                ldsm_x4(a[0], a[1], a[2], a[3],
                        vtBase + (uint32_t)(dt * 16 * VT_S * 2) + kOrgB);
                mma_f16(av[dt][0], a, bq0);
                mma_f16(av[dt][1], a, bq1);
            }
        }

        // combine k-halves: wn=0 stores partial, wn=1 adds and writes ctx
        if (wn == 0) {
#pragma unroll
            for (int dt = 0; dt < 4; dt++)
#pragma unroll
                for (int qg = 0; qg < 2; qg++) {
                    const int ql = qg * 8 + 2 * tig;
                    float* p0 = part + ((wm * 64 + dt * 16 + g    ) * 17 + ql);
                    float* p1 = part + ((wm * 64 + dt * 16 + g + 8) * 17 + ql);
                    p0[0] = av[dt][qg][0]; p0[1] = av[dt][qg][1];
                    p1[0] = av[dt][qg][2]; p1[1] = av[dt][qg][3];
                }
        }
        __syncthreads();
        if (wn == 1) {
#pragma unroll
            for (int dt = 0; dt < 4; dt++)
#pragma unroll
                for (int qg = 0; qg < 2; qg++) {
                    const int ql = qg * 8 + 2 * tig;
                    const float* p0 = part + ((wm * 64 + dt * 16 + g    ) * 17 + ql);
                    const float* p1 = part + ((wm * 64 + dt * 16 + g + 8) * 17 + ql);
                    const int d0 = dt * 16 + g;
                    const int d1 = d0 + 8;
#pragma unroll
                    for (int dq = 0; dq < 2; dq++) {
                        const int q = qbase + rB + ql + dq;
                        if (q < HW) {
                            __half* dst = ctx + (size_t)(b * HW + q) * C_DIM + h * HD;
                            dst[d0] = __float2half(av[dt][qg][dq]     + p0[dq]);
                            dst[d1] = __float2half(av[dt][qg][2 + dq] + p1[dq]);
                        }
                    }
                }
        }
    }
}

// ---------------------------------------------------------------------------
extern "C" void kernel_launch(void* const* d_in, const int* in_sizes, int n_in,
                              void* d_out, int out_size) {
    const float* x      = (const float*)d_in[0];
    const float* w_qkv  = (const float*)d_in[1];
    const float* b_qkv  = (const float*)d_in[2];
    const float* w_proj = (const float*)d_in[3];
    const float* b_proj = (const float*)d_in[4];
    const float* rph    = (const float*)d_in[5];
    const float* rpw    = (const float*)d_in[6];
    float* out = (float*)d_out;

    __half *qkvh, *xc, *ctx, *wqT, *wpT;
    cudaGetSymbolAddress((void**)&qkvh, g_qkvh);
    cudaGetSymbolAddress((void**)&xc, g_xc);
    cudaGetSymbolAddress((void**)&ctx, g_ctx);
    cudaGetSymbolAddress((void**)&wqT, g_wqT);
    cudaGetSymbolAddress((void**)&wpT, g_wpT);

    static bool attr_set = false;
    if (!attr_set) {
        cudaFuncSetAttribute(gemm_f16_bias_t<__half>,
                             cudaFuncAttributeMaxDynamicSharedMemorySize,
                             GH_SMEM_BYTES);
        cudaFuncSetAttribute(gemm_f16_bias_t<float>,
                             cudaFuncAttributeMaxDynamicSharedMemorySize,
                             GH_SMEM_BYTES);
        cudaFuncSetAttribute(attn_fused_kernel,
                             cudaFuncAttributeMaxDynamicSharedMemorySize,
                             F_SMEM_BYTES);
        attr_set = true;
    }

    // 0) Pre-pass: fp16-convert x; transpose + fp16 weights
    cvt_half_kernel<<<592, 256>>>(x, xc, M_TOK * C_DIM / 4);
    {
        dim3 blk(32, 8);
        dim3 gq(QKV_N / 32, C_DIM / 32);
        transpose_half_kernel<<<gq, blk>>>(w_qkv, wqT, C_DIM, QKV_N);
        dim3 gp(C_DIM / 32, C_DIM / 32);
        transpose_half_kernel<<<gp, blk>>>(w_proj, wpT, C_DIM, C_DIM);
    }

    // 1) QKV projection (fp16 mma, fp16 output)
    {
        dim3 grid(QKV_N / BNH, (M_TOK + BMH - 1) / BMH);   // 18 x 307
        gemm_f16_bias_t<__half><<<grid, 256, GH_SMEM_BYTES>>>(xc, wqT, b_qkv, qkvh,
                                                              M_TOK, QKV_N, C_DIM);
    }

    // 2) Fused attention (logits + softmax + AV), ctx fp16
    attn_fused_kernel<<<NHEADS_TOT, 256, F_SMEM_BYTES>>>(qkvh, rph, rpw, ctx);

    // 3) Output projection (fp16 mma, fp32 output)
    {
        dim3 grid(C_DIM / BNH, (M_TOK + BMH - 1) / BMH);   // 6 x 307
        gemm_f16_bias_t<float><<<grid, 256, GH_SMEM_BYTES>>>(ctx, wpT, b_proj, out,
                                                             M_TOK, C_DIM, C_DIM);
    }
}